// round 3
// baseline (speedup 1.0000x reference)
#include <cuda_runtime.h>
#include <math.h>

// Problem dims
#define NB 8
#define LQ 1024
#define SK 4096
#define DM 512

// Scratch (device globals: no allocations allowed)
__device__ float g_q [NB*LQ*DM];
__device__ float g_k [NB*SK*DM];
__device__ float g_v [NB*SK*DM];
__device__ float g_q2[NB*LQ];
__device__ float g_k2[NB*SK];
__device__ float g_sc[(size_t)NB*LQ*SK];   // dist, then attn in-place
__device__ float g_ms[NB*LQ*DM];           // attn @ v
__device__ float g_mm[NB*LQ*DM];           // (attn@v) @ Wm
__device__ float g_m1[NB*LQ*DM];           // layernorm1 output
__device__ float g_u [NB*LQ*2*DM];         // relu(concat @ W1)
__device__ float g_z [NB*LQ*DM];           // u @ W2

// ---------------------------------------------------------------------------
// Generic 128x128x8 register-blocked SGEMM, 256 threads, 8x8 per thread.
// MODE 0: C = A(row,MxK) @ B(row,KxN)
// MODE 1: NT gemm (B is row-major [N,K]); epilogue dist = sqrt(max(e0[m]+e1[n]-2*acc, 0))
// MODE 2: A is virtual concat [A | A1] along K (each half lda=512); epilogue relu
// Batched via blockIdx.z with element strides sA/sB/sC (0 for shared weights).
// All dims are multiples of tile sizes for this problem (no bounds checks).
// ---------------------------------------------------------------------------
template<int MODE>
__global__ __launch_bounds__(256)
void sgemm_k(const float* __restrict__ A, const float* __restrict__ A1,
             const float* __restrict__ B, float* __restrict__ C,
             int M, int N, int K, int lda, int ldb, int ldc,
             long sA, long sB, long sC,
             const float* __restrict__ e0, const float* __restrict__ e1,
             int se0, int se1)
{
    __shared__ float As[8][128];
    __shared__ float Bs[8][128];

    const int z = blockIdx.z;
    A += (long)z * sA;
    if (MODE == 2) A1 += (long)z * sA;
    B += (long)z * sB;
    C += (long)z * sC;
    const float* E0 = (MODE == 1) ? (e0 + (long)z * se0) : nullptr;
    const float* E1 = (MODE == 1) ? (e1 + (long)z * se1) : nullptr;

    const int t  = threadIdx.x;
    const int m0 = blockIdx.y * 128;
    const int n0 = blockIdx.x * 128;
    const int ty = t >> 4, tx = t & 15;

    float acc[8][8];
#pragma unroll
    for (int i = 0; i < 8; i++)
#pragma unroll
        for (int j = 0; j < 8; j++) acc[i][j] = 0.f;

    const int arow = t >> 1, ac4 = (t & 1) * 4;
    int brow, bc4;
    if (MODE == 1) { brow = t >> 1;  bc4 = (t & 1) * 4;  }
    else           { brow = t >> 5;  bc4 = (t & 31) * 4; }

    for (int k0 = 0; k0 < K; k0 += 8) {
        // --- A tile: rows m0..m0+127, cols k0..k0+7 -> As[k][m] (transposed)
        const float* Asrc = A;
        int kk0 = k0;
        if (MODE == 2 && k0 >= 512) { Asrc = A1; kk0 = k0 - 512; }
        float4 av = *reinterpret_cast<const float4*>(Asrc + (long)(m0 + arow) * lda + kk0 + ac4);
        As[ac4 + 0][arow] = av.x; As[ac4 + 1][arow] = av.y;
        As[ac4 + 2][arow] = av.z; As[ac4 + 3][arow] = av.w;

        // --- B tile
        if (MODE == 1) {
            // B row-major [N,K]: rows n0..n0+127, cols k0..k0+7 -> Bs[k][n]
            float4 bv = *reinterpret_cast<const float4*>(B + (long)(n0 + brow) * ldb + k0 + bc4);
            Bs[bc4 + 0][brow] = bv.x; Bs[bc4 + 1][brow] = bv.y;
            Bs[bc4 + 2][brow] = bv.z; Bs[bc4 + 3][brow] = bv.w;
        } else {
            // B row-major [K,N]: rows k0..k0+7, cols n0..n0+127 -> Bs[k][n]
            float4 bv = *reinterpret_cast<const float4*>(B + (long)(k0 + brow) * ldb + n0 + bc4);
            *reinterpret_cast<float4*>(&Bs[brow][bc4]) = bv;
        }
        __syncthreads();

#pragma unroll
        for (int kk = 0; kk < 8; kk++) {
            float a[8], b[8];
#pragma unroll
            for (int i = 0; i < 8; i++) a[i] = As[kk][ty * 8 + i];
#pragma unroll
            for (int j = 0; j < 8; j++) b[j] = Bs[kk][tx * 8 + j];
#pragma unroll
            for (int i = 0; i < 8; i++)
#pragma unroll
                for (int j = 0; j < 8; j++) acc[i][j] = fmaf(a[i], b[j], acc[i][j]);
        }
        __syncthreads();
    }

    // --- epilogue
#pragma unroll
    for (int i = 0; i < 8; i++) {
        const int m = m0 + ty * 8 + i;
#pragma unroll
        for (int j = 0; j < 8; j++) {
            const int n = n0 + tx * 8 + j;
            float val = acc[i][j];
            if (MODE == 1) val = sqrtf(fmaxf(E0[m] + E1[n] - 2.f * val, 0.f));
            if (MODE == 2) val = fmaxf(val, 0.f);
            C[(long)m * ldc + n] = val;
        }
    }
}

// Row squared-norms: one warp per row, cols = 512
__global__ __launch_bounds__(256)
void rownorm_k(const float* __restrict__ X, float* __restrict__ out, int cols)
{
    const int row  = blockIdx.x * 8 + (threadIdx.x >> 5);
    const int lane = threadIdx.x & 31;
    const float* p = X + (long)row * cols;
    float s = 0.f;
    for (int c = lane; c < cols; c += 32) { float v = p[c]; s = fmaf(v, v, s); }
#pragma unroll
    for (int o = 16; o; o >>= 1) s += __shfl_xor_sync(0xffffffffu, s, o);
    if (lane == 0) out[row] = s;
}

// Softmax over rows of 4096 (in-place), one block per row
__global__ __launch_bounds__(256)
void softmax_k(float* __restrict__ sc)
{
    float* p = sc + (long)blockIdx.x * 4096;
    const int t = threadIdx.x;
    float vals[16];
    float mx = -1e30f;
#pragma unroll
    for (int i = 0; i < 16; i++) { vals[i] = p[t + i * 256]; mx = fmaxf(mx, vals[i]); }
    __shared__ float red[256];
    red[t] = mx; __syncthreads();
    for (int o = 128; o; o >>= 1) { if (t < o) red[t] = fmaxf(red[t], red[t + o]); __syncthreads(); }
    mx = red[0]; __syncthreads();
    float s = 0.f;
#pragma unroll
    for (int i = 0; i < 16; i++) { vals[i] = __expf(vals[i] - mx); s += vals[i]; }
    red[t] = s; __syncthreads();
    for (int o = 128; o; o >>= 1) { if (t < o) red[t] += red[t + o]; __syncthreads(); }
    const float inv = 1.f / red[0];
#pragma unroll
    for (int i = 0; i < 16; i++) p[t + i * 256] = vals[i] * inv;
}

// LayerNorm over rows of 512; optional residual add. One block per row.
__global__ __launch_bounds__(256)
void ln_k(const float* __restrict__ X, const float* __restrict__ g,
          const float* __restrict__ b, const float* __restrict__ res,
          float* __restrict__ out)
{
    const long row = blockIdx.x;
    const float* p = X + row * 512;
    const int t = threadIdx.x;
    float v0 = p[t], v1 = p[t + 256];
    __shared__ float red[256];
    red[t] = v0 + v1; __syncthreads();
    for (int o = 128; o; o >>= 1) { if (t < o) red[t] += red[t + o]; __syncthreads(); }
    const float mu = red[0] * (1.f / 512.f);
    __syncthreads();
    const float d0 = v0 - mu, d1 = v1 - mu;
    red[t] = d0 * d0 + d1 * d1; __syncthreads();
    for (int o = 128; o; o >>= 1) { if (t < o) red[t] += red[t + o]; __syncthreads(); }
    const float rs = rsqrtf(red[0] * (1.f / 512.f) + 1e-5f);
    float o0 = d0 * rs * g[t]       + b[t];
    float o1 = d1 * rs * g[t + 256] + b[t + 256];
    if (res) { o0 += res[row * 512 + t]; o1 += res[row * 512 + t + 256]; }
    out[row * 512 + t]       = o0;
    out[row * 512 + t + 256] = o1;
}

template <typename T>
static float* sym(T& s) { void* p = nullptr; cudaGetSymbolAddress(&p, s); return (float*)p; }

extern "C" void kernel_launch(void* const* d_in, const int* in_sizes, int n_in,
                              void* d_out, int out_size)
{
    const float* x   = (const float*)d_in[0];
    const float* src = (const float*)d_in[1];
    const float* Wq  = (const float*)d_in[2];
    const float* Wk  = (const float*)d_in[3];
    const float* Wv  = (const float*)d_in[4];
    const float* Wm  = (const float*)d_in[5];
    const float* W1  = (const float*)d_in[6];
    const float* W2  = (const float*)d_in[7];
    const float* g1  = (const float*)d_in[8];
    const float* b1  = (const float*)d_in[9];
    const float* g2  = (const float*)d_in[10];
    const float* b2  = (const float*)d_in[11];
    float* out = (float*)d_out;

    float *q  = sym(g_q),  *k  = sym(g_k),  *v  = sym(g_v);
    float *q2 = sym(g_q2), *k2 = sym(g_k2), *sc = sym(g_sc);
    float *ms = sym(g_ms), *mm = sym(g_mm), *m1 = sym(g_m1);
    float *u  = sym(g_u),  *zz = sym(g_z);

    const int ML = NB * LQ;   // 8192
    const int MS = NB * SK;   // 32768

    // 1-3: q/k/v projections (flattened over batch; weights shared)
    sgemm_k<0><<<dim3(DM/128, ML/128, 1), 256>>>(x,   nullptr, Wq, q, ML, DM, DM, DM, DM, DM, 0, 0, 0, nullptr, nullptr, 0, 0);
    sgemm_k<0><<<dim3(DM/128, MS/128, 1), 256>>>(src, nullptr, Wk, k, MS, DM, DM, DM, DM, DM, 0, 0, 0, nullptr, nullptr, 0, 0);
    sgemm_k<0><<<dim3(DM/128, MS/128, 1), 256>>>(src, nullptr, Wv, v, MS, DM, DM, DM, DM, DM, 0, 0, 0, nullptr, nullptr, 0, 0);

    // 4-5: squared row norms
    rownorm_k<<<ML / 8, 256>>>(q, q2, DM);
    rownorm_k<<<MS / 8, 256>>>(k, k2, DM);

    // 6: dist = sqrt(max(q2 + k2 - 2 q.k, 0))   (batched NT gemm, fused epilogue)
    sgemm_k<1><<<dim3(SK/128, LQ/128, NB), 256>>>(q, nullptr, k, sc,
        LQ, SK, DM, DM, DM, SK,
        (long)LQ*DM, (long)SK*DM, (long)LQ*SK, q2, k2, LQ, SK);

    // 7: softmax over S (in-place)
    softmax_k<<<ML, 256>>>(sc);

    // 8: message = attn @ v   (batched NN gemm)
    sgemm_k<0><<<dim3(DM/128, LQ/128, NB), 256>>>(sc, nullptr, v, ms,
        LQ, DM, SK, SK, DM, DM,
        (long)LQ*SK, (long)SK*DM, (long)LQ*DM, nullptr, nullptr, 0, 0);

    // 9: message @ Wm
    sgemm_k<0><<<dim3(DM/128, ML/128, 1), 256>>>(ms, nullptr, Wm, mm, ML, DM, DM, DM, DM, DM, 0, 0, 0, nullptr, nullptr, 0, 0);

    // 10: layernorm1
    ln_k<<<ML, 256>>>(mm, g1, b1, nullptr, m1);

    // 11: u = relu([x | m1] @ W1)   (fused concat + relu)
    sgemm_k<2><<<dim3(2*DM/128, ML/128, 1), 256>>>(x, m1, W1, u, ML, 2*DM, 2*DM, DM, 2*DM, 2*DM, 0, 0, 0, nullptr, nullptr, 0, 0);

    // 12: z = u @ W2
    sgemm_k<0><<<dim3(DM/128, ML/128, 1), 256>>>(u, nullptr, W2, zz, ML, DM, 2*DM, 2*DM, DM, DM, 0, 0, 0, nullptr, nullptr, 0, 0);

    // 13: out = x + layernorm2(z)
    ln_k<<<ML, 256>>>(zz, g2, b2, x, out);
}

// round 4
// speedup vs baseline: 2.5551x; 2.5551x over previous
#include <cuda_runtime.h>
#include <math.h>

// Problem dims
#define NB 8
#define LQ 1024
#define SK 4096
#define DM 512

// Scratch (device globals: no allocations allowed)
__device__ float g_q [NB*LQ*DM];
__device__ float g_k [NB*SK*DM];
__device__ float g_v [NB*SK*DM];
__device__ float g_q2[NB*LQ];
__device__ float g_k2[NB*SK];
__device__ float g_sc[(size_t)NB*LQ*SK];   // dist, then attn in-place
__device__ float g_ms[NB*LQ*DM];           // attn @ v
__device__ float g_mm[NB*LQ*DM];           // (attn@v) @ Wm
__device__ float g_m1[NB*LQ*DM];           // layernorm1 output
__device__ float g_u [NB*LQ*2*DM];         // relu(concat @ W1)
__device__ float g_z [NB*LQ*DM];           // u @ W2

// ---------------------------------------------------------------------------
// tf32 tensor-core GEMM: 128x128 block tile, BK=16, double-buffered smem,
// 256 threads = 8 warps arranged 4x2, each warp owns a 32x64 tile computed
// with mma.sync.aligned.m16n8k8.row.col.f32.tf32.tf32.f32.
// MODE 0: C = A(row,MxK) @ B(row,KxN)
// MODE 1: NT gemm (B row-major [N,K]); epilogue dist = sqrt(max(e0[m]+e1[n]-2*acc,0))
// MODE 2: A is virtual concat [A | A1] along K (each half lda=512); epilogue relu
// Batched via blockIdx.z with element strides sA/sB/sC (0 for shared weights).
// All dims are multiples of the tile sizes for this problem.
// ---------------------------------------------------------------------------

__device__ __forceinline__ float f2tf32(float x) {
    unsigned y;
    asm("cvt.rna.tf32.f32 %0, %1;" : "=r"(y) : "f"(x));
    return __uint_as_float(y);
}

__device__ __forceinline__ void mma_tf32(float c[4], const unsigned a[4], const unsigned b[2]) {
    asm("mma.sync.aligned.m16n8k8.row.col.f32.tf32.tf32.f32 "
        "{%0,%1,%2,%3}, {%4,%5,%6,%7}, {%8,%9}, {%0,%1,%2,%3};"
        : "+f"(c[0]), "+f"(c[1]), "+f"(c[2]), "+f"(c[3])
        : "r"(a[0]), "r"(a[1]), "r"(a[2]), "r"(a[3]), "r"(b[0]), "r"(b[1]));
}

#define SPAD 132   // 128 + 4 float padding (keeps 16B alignment, breaks conflicts)

template<int MODE>
__global__ __launch_bounds__(256)
void tgemm_k(const float* __restrict__ A, const float* __restrict__ A1,
             const float* __restrict__ B, float* __restrict__ C,
             int M, int N, int K, int lda, int ldb, int ldc,
             long sA, long sB, long sC,
             const float* __restrict__ e0, const float* __restrict__ e1,
             int se0, int se1)
{
    __shared__ float As[2][16][SPAD];
    __shared__ float Bs[2][16][SPAD];

    const int z = blockIdx.z;
    A += (long)z * sA;
    if (MODE == 2) A1 += (long)z * sA;
    B += (long)z * sB;
    C += (long)z * sC;
    const float* E0 = (MODE == 1) ? (e0 + (long)z * se0) : nullptr;
    const float* E1 = (MODE == 1) ? (e1 + (long)z * se1) : nullptr;

    const int t  = threadIdx.x;
    const int m0 = blockIdx.y * 128;
    const int n0 = blockIdx.x * 128;

    const int warpId = t >> 5;
    const int lane   = t & 31;
    const int warpM  = warpId >> 1;          // 0..3
    const int warpN  = warpId & 1;           // 0..1
    const int mb     = warpM * 32;
    const int nb     = warpN * 64;
    const int gq     = lane >> 2;            // group id 0..7
    const int tg     = lane & 3;             // thread-in-group 0..3

    // A tile chunk mapping: 512 float4-chunks, this thread: c = t, t+256
    const int a_row0 = t >> 2,        a_c4 = (t & 3) * 4;
    const int a_row1 = (t + 256) >> 2;
    // B mode0 chunk mapping: row k = c>>5, col4 = (c&31)*4
    const int b0_row0 = t >> 5,       b0_c4  = (t & 31) * 4;
    const int b0_row1 = (t + 256) >> 5;
    // B mode1 chunk mapping (row-major [N,K]): n = c>>2, col4 = (c&3)*4
    const int b1_n0 = t >> 2,         b1_c4 = (t & 3) * 4;
    const int b1_n1 = (t + 256) >> 2;

    float acc[2][8][4];
#pragma unroll
    for (int i = 0; i < 2; i++)
#pragma unroll
        for (int j = 0; j < 8; j++)
#pragma unroll
            for (int r = 0; r < 4; r++) acc[i][j][r] = 0.f;

    // ---- prologue: load tile k0=0 into buffer 0
    {
        const float* Asrc = A; int kk0 = 0;
        float4 av0 = *reinterpret_cast<const float4*>(Asrc + (long)(m0 + a_row0) * lda + kk0 + a_c4);
        float4 av1 = *reinterpret_cast<const float4*>(Asrc + (long)(m0 + a_row1) * lda + kk0 + a_c4);
        As[0][a_c4 + 0][a_row0] = f2tf32(av0.x); As[0][a_c4 + 1][a_row0] = f2tf32(av0.y);
        As[0][a_c4 + 2][a_row0] = f2tf32(av0.z); As[0][a_c4 + 3][a_row0] = f2tf32(av0.w);
        As[0][a_c4 + 0][a_row1] = f2tf32(av1.x); As[0][a_c4 + 1][a_row1] = f2tf32(av1.y);
        As[0][a_c4 + 2][a_row1] = f2tf32(av1.z); As[0][a_c4 + 3][a_row1] = f2tf32(av1.w);
        if (MODE == 1) {
            float4 bv0 = *reinterpret_cast<const float4*>(B + (long)(n0 + b1_n0) * ldb + 0 + b1_c4);
            float4 bv1 = *reinterpret_cast<const float4*>(B + (long)(n0 + b1_n1) * ldb + 0 + b1_c4);
            Bs[0][b1_c4 + 0][b1_n0] = f2tf32(bv0.x); Bs[0][b1_c4 + 1][b1_n0] = f2tf32(bv0.y);
            Bs[0][b1_c4 + 2][b1_n0] = f2tf32(bv0.z); Bs[0][b1_c4 + 3][b1_n0] = f2tf32(bv0.w);
            Bs[0][b1_c4 + 0][b1_n1] = f2tf32(bv1.x); Bs[0][b1_c4 + 1][b1_n1] = f2tf32(bv1.y);
            Bs[0][b1_c4 + 2][b1_n1] = f2tf32(bv1.z); Bs[0][b1_c4 + 3][b1_n1] = f2tf32(bv1.w);
        } else {
            float4 bv0 = *reinterpret_cast<const float4*>(B + (long)(0 + b0_row0) * ldb + n0 + b0_c4);
            float4 bv1 = *reinterpret_cast<const float4*>(B + (long)(0 + b0_row1) * ldb + n0 + b0_c4);
            float4 s0 = make_float4(f2tf32(bv0.x), f2tf32(bv0.y), f2tf32(bv0.z), f2tf32(bv0.w));
            float4 s1 = make_float4(f2tf32(bv1.x), f2tf32(bv1.y), f2tf32(bv1.z), f2tf32(bv1.w));
            *reinterpret_cast<float4*>(&Bs[0][b0_row0][b0_c4]) = s0;
            *reinterpret_cast<float4*>(&Bs[0][b0_row1][b0_c4]) = s1;
        }
    }
    __syncthreads();

    int buf = 0;
    for (int k0 = 0; k0 < K; k0 += 16) {
        const bool last = (k0 + 16 >= K);
        float4 av0, av1, bv0, bv1;
        if (!last) {
            const int kn = k0 + 16;
            const float* Asrc = A; int kk0 = kn;
            if (MODE == 2 && kn >= 512) { Asrc = A1; kk0 = kn - 512; }
            av0 = *reinterpret_cast<const float4*>(Asrc + (long)(m0 + a_row0) * lda + kk0 + a_c4);
            av1 = *reinterpret_cast<const float4*>(Asrc + (long)(m0 + a_row1) * lda + kk0 + a_c4);
            if (MODE == 1) {
                bv0 = *reinterpret_cast<const float4*>(B + (long)(n0 + b1_n0) * ldb + kn + b1_c4);
                bv1 = *reinterpret_cast<const float4*>(B + (long)(n0 + b1_n1) * ldb + kn + b1_c4);
            } else {
                bv0 = *reinterpret_cast<const float4*>(B + (long)(kn + b0_row0) * ldb + n0 + b0_c4);
                bv1 = *reinterpret_cast<const float4*>(B + (long)(kn + b0_row1) * ldb + n0 + b0_c4);
            }
        }

        // ---- compute two k-steps of 8 on current buffer
#pragma unroll
        for (int ks = 0; ks < 16; ks += 8) {
            unsigned a[2][4], b[8][2];
#pragma unroll
            for (int i = 0; i < 2; i++) {
                const int m = mb + i * 16 + gq;
                a[i][0] = __float_as_uint(As[buf][ks + tg    ][m    ]);
                a[i][1] = __float_as_uint(As[buf][ks + tg    ][m + 8]);
                a[i][2] = __float_as_uint(As[buf][ks + tg + 4][m    ]);
                a[i][3] = __float_as_uint(As[buf][ks + tg + 4][m + 8]);
            }
#pragma unroll
            for (int j = 0; j < 8; j++) {
                const int n = nb + j * 8 + gq;
                b[j][0] = __float_as_uint(Bs[buf][ks + tg    ][n]);
                b[j][1] = __float_as_uint(Bs[buf][ks + tg + 4][n]);
            }
#pragma unroll
            for (int i = 0; i < 2; i++)
#pragma unroll
                for (int j = 0; j < 8; j++)
                    mma_tf32(acc[i][j], a[i], b[j]);
        }

        if (!last) {
            const int nx = buf ^ 1;
            As[nx][a_c4 + 0][a_row0] = f2tf32(av0.x); As[nx][a_c4 + 1][a_row0] = f2tf32(av0.y);
            As[nx][a_c4 + 2][a_row0] = f2tf32(av0.z); As[nx][a_c4 + 3][a_row0] = f2tf32(av0.w);
            As[nx][a_c4 + 0][a_row1] = f2tf32(av1.x); As[nx][a_c4 + 1][a_row1] = f2tf32(av1.y);
            As[nx][a_c4 + 2][a_row1] = f2tf32(av1.z); As[nx][a_c4 + 3][a_row1] = f2tf32(av1.w);
            if (MODE == 1) {
                Bs[nx][b1_c4 + 0][b1_n0] = f2tf32(bv0.x); Bs[nx][b1_c4 + 1][b1_n0] = f2tf32(bv0.y);
                Bs[nx][b1_c4 + 2][b1_n0] = f2tf32(bv0.z); Bs[nx][b1_c4 + 3][b1_n0] = f2tf32(bv0.w);
                Bs[nx][b1_c4 + 0][b1_n1] = f2tf32(bv1.x); Bs[nx][b1_c4 + 1][b1_n1] = f2tf32(bv1.y);
                Bs[nx][b1_c4 + 2][b1_n1] = f2tf32(bv1.z); Bs[nx][b1_c4 + 3][b1_n1] = f2tf32(bv1.w);
            } else {
                float4 s0 = make_float4(f2tf32(bv0.x), f2tf32(bv0.y), f2tf32(bv0.z), f2tf32(bv0.w));
                float4 s1 = make_float4(f2tf32(bv1.x), f2tf32(bv1.y), f2tf32(bv1.z), f2tf32(bv1.w));
                *reinterpret_cast<float4*>(&Bs[nx][b0_row0][b0_c4]) = s0;
                *reinterpret_cast<float4*>(&Bs[nx][b0_row1][b0_c4]) = s1;
            }
            __syncthreads();
            buf ^= 1;
        }
    }

    // ---- epilogue
#pragma unroll
    for (int i = 0; i < 2; i++) {
        const int row0 = m0 + mb + i * 16 + gq;
        const int row1 = row0 + 8;
#pragma unroll
        for (int j = 0; j < 8; j++) {
            const int col0 = n0 + nb + j * 8 + tg * 2;
            float v00 = acc[i][j][0], v01 = acc[i][j][1];
            float v10 = acc[i][j][2], v11 = acc[i][j][3];
            if (MODE == 1) {
                const float e00 = E0[row0], e01 = E0[row1];
                const float f0 = E1[col0], f1 = E1[col0 + 1];
                v00 = sqrtf(fmaxf(e00 + f0 - 2.f * v00, 0.f));
                v01 = sqrtf(fmaxf(e00 + f1 - 2.f * v01, 0.f));
                v10 = sqrtf(fmaxf(e01 + f0 - 2.f * v10, 0.f));
                v11 = sqrtf(fmaxf(e01 + f1 - 2.f * v11, 0.f));
            }
            if (MODE == 2) {
                v00 = fmaxf(v00, 0.f); v01 = fmaxf(v01, 0.f);
                v10 = fmaxf(v10, 0.f); v11 = fmaxf(v11, 0.f);
            }
            *reinterpret_cast<float2*>(C + (long)row0 * ldc + col0) = make_float2(v00, v01);
            *reinterpret_cast<float2*>(C + (long)row1 * ldc + col0) = make_float2(v10, v11);
        }
    }
}

// Row squared-norms: one warp per row, cols = 512
__global__ __launch_bounds__(256)
void rownorm_k(const float* __restrict__ X, float* __restrict__ out, int cols)
{
    const int row  = blockIdx.x * 8 + (threadIdx.x >> 5);
    const int lane = threadIdx.x & 31;
    const float* p = X + (long)row * cols;
    float s = 0.f;
    for (int c = lane; c < cols; c += 32) { float v = p[c]; s = fmaf(v, v, s); }
#pragma unroll
    for (int o = 16; o; o >>= 1) s += __shfl_xor_sync(0xffffffffu, s, o);
    if (lane == 0) out[row] = s;
}

// Softmax over rows of 4096 (in-place), one block per row
__global__ __launch_bounds__(256)
void softmax_k(float* __restrict__ sc)
{
    float* p = sc + (long)blockIdx.x * 4096;
    const int t = threadIdx.x;
    float vals[16];
    float mx = -1e30f;
#pragma unroll
    for (int i = 0; i < 16; i++) { vals[i] = p[t + i * 256]; mx = fmaxf(mx, vals[i]); }
    __shared__ float red[256];
    red[t] = mx; __syncthreads();
    for (int o = 128; o; o >>= 1) { if (t < o) red[t] = fmaxf(red[t], red[t + o]); __syncthreads(); }
    mx = red[0]; __syncthreads();
    float s = 0.f;
#pragma unroll
    for (int i = 0; i < 16; i++) { vals[i] = __expf(vals[i] - mx); s += vals[i]; }
    red[t] = s; __syncthreads();
    for (int o = 128; o; o >>= 1) { if (t < o) red[t] += red[t + o]; __syncthreads(); }
    const float inv = 1.f / red[0];
#pragma unroll
    for (int i = 0; i < 16; i++) p[t + i * 256] = vals[i] * inv;
}

// LayerNorm over rows of 512; optional residual add. One block per row.
__global__ __launch_bounds__(256)
void ln_k(const float* __restrict__ X, const float* __restrict__ g,
          const float* __restrict__ b, const float* __restrict__ res,
          float* __restrict__ out)
{
    const long row = blockIdx.x;
    const float* p = X + row * 512;
    const int t = threadIdx.x;
    float v0 = p[t], v1 = p[t + 256];
    __shared__ float red[256];
    red[t] = v0 + v1; __syncthreads();
    for (int o = 128; o; o >>= 1) { if (t < o) red[t] += red[t + o]; __syncthreads(); }
    const float mu = red[0] * (1.f / 512.f);
    __syncthreads();
    const float d0 = v0 - mu, d1 = v1 - mu;
    red[t] = d0 * d0 + d1 * d1; __syncthreads();
    for (int o = 128; o; o >>= 1) { if (t < o) red[t] += red[t + o]; __syncthreads(); }
    const float rs = rsqrtf(red[0] * (1.f / 512.f) + 1e-5f);
    float o0 = d0 * rs * g[t]       + b[t];
    float o1 = d1 * rs * g[t + 256] + b[t + 256];
    if (res) { o0 += res[row * 512 + t]; o1 += res[row * 512 + t + 256]; }
    out[row * 512 + t]       = o0;
    out[row * 512 + t + 256] = o1;
}

template <typename T>
static float* sym(T& s) { void* p = nullptr; cudaGetSymbolAddress(&p, s); return (float*)p; }

extern "C" void kernel_launch(void* const* d_in, const int* in_sizes, int n_in,
                              void* d_out, int out_size)
{
    const float* x   = (const float*)d_in[0];
    const float* src = (const float*)d_in[1];
    const float* Wq  = (const float*)d_in[2];
    const float* Wk  = (const float*)d_in[3];
    const float* Wv  = (const float*)d_in[4];
    const float* Wm  = (const float*)d_in[5];
    const float* W1  = (const float*)d_in[6];
    const float* W2  = (const float*)d_in[7];
    const float* g1  = (const float*)d_in[8];
    const float* b1  = (const float*)d_in[9];
    const float* g2  = (const float*)d_in[10];
    const float* b2  = (const float*)d_in[11];
    float* out = (float*)d_out;

    float *q  = sym(g_q),  *k  = sym(g_k),  *v  = sym(g_v);
    float *q2 = sym(g_q2), *k2 = sym(g_k2), *sc = sym(g_sc);
    float *ms = sym(g_ms), *mm = sym(g_mm), *m1 = sym(g_m1);
    float *u  = sym(g_u),  *zz = sym(g_z);

    const int ML = NB * LQ;   // 8192
    const int MS = NB * SK;   // 32768

    // 1-3: q/k/v projections (flattened over batch; weights shared)
    tgemm_k<0><<<dim3(DM/128, ML/128, 1), 256>>>(x,   nullptr, Wq, q, ML, DM, DM, DM, DM, DM, 0, 0, 0, nullptr, nullptr, 0, 0);
    tgemm_k<0><<<dim3(DM/128, MS/128, 1), 256>>>(src, nullptr, Wk, k, MS, DM, DM, DM, DM, DM, 0, 0, 0, nullptr, nullptr, 0, 0);
    tgemm_k<0><<<dim3(DM/128, MS/128, 1), 256>>>(src, nullptr, Wv, v, MS, DM, DM, DM, DM, DM, 0, 0, 0, nullptr, nullptr, 0, 0);

    // 4-5: squared row norms (fp32 exact)
    rownorm_k<<<ML / 8, 256>>>(q, q2, DM);
    rownorm_k<<<MS / 8, 256>>>(k, k2, DM);

    // 6: dist = sqrt(max(q2 + k2 - 2 q.k, 0))   (batched NT gemm, fused epilogue)
    tgemm_k<1><<<dim3(SK/128, LQ/128, NB), 256>>>(q, nullptr, k, sc,
        LQ, SK, DM, DM, DM, SK,
        (long)LQ*DM, (long)SK*DM, (long)LQ*SK, q2, k2, LQ, SK);

    // 7: softmax over S (in-place)
    softmax_k<<<ML, 256>>>(sc);

    // 8: message = attn @ v   (batched NN gemm)
    tgemm_k<0><<<dim3(DM/128, LQ/128, NB), 256>>>(sc, nullptr, v, ms,
        LQ, DM, SK, SK, DM, DM,
        (long)LQ*SK, (long)SK*DM, (long)LQ*DM, nullptr, nullptr, 0, 0);

    // 9: message @ Wm
    tgemm_k<0><<<dim3(DM/128, ML/128, 1), 256>>>(ms, nullptr, Wm, mm, ML, DM, DM, DM, DM, DM, 0, 0, 0, nullptr, nullptr, 0, 0);

    // 10: layernorm1
    ln_k<<<ML, 256>>>(mm, g1, b1, nullptr, m1);

    // 11: u = relu([x | m1] @ W1)   (fused concat + relu)
    tgemm_k<2><<<dim3(2*DM/128, ML/128, 1), 256>>>(x, m1, W1, u, ML, 2*DM, 2*DM, DM, 2*DM, 2*DM, 0, 0, 0, nullptr, nullptr, 0, 0);

    // 12: z = u @ W2
    tgemm_k<0><<<dim3(DM/128, ML/128, 1), 256>>>(u, nullptr, W2, zz, ML, DM, 2*DM, 2*DM, DM, DM, 0, 0, 0, nullptr, nullptr, 0, 0);

    // 13: out = x + layernorm2(z)
    ln_k<<<ML, 256>>>(zz, g2, b2, x, out);
}

// round 8
// speedup vs baseline: 3.6201x; 1.4168x over previous
#include <cuda_runtime.h>
#include <cuda_fp16.h>
#include <math.h>
#include <stdint.h>

// Problem dims
#define NB 8
#define LQ 1024
#define SK 4096
#define DM 512
#define ML (NB*LQ)   // 8192
#define MS (NB*SK)   // 32768
#define BKH 32       // k-chunk (halves) per buffer = two k16 MMA steps
#define PADK 40      // padded row stride in halves (conflict-free fragment LDS)

// ---------------------------------------------------------------------------
// Scratch (device globals: no allocations allowed)
// ---------------------------------------------------------------------------
__device__ float g_q  [ML*DM];
__device__ float g_k  [MS*DM];
__device__ float g_v  [MS*DM];
__device__ float g_vT [(size_t)NB*DM*SK];
__device__ float g_q2 [ML];
__device__ float g_k2 [MS];
__device__ float g_sc [(size_t)NB*LQ*SK];
__device__ float g_ms [ML*DM];
__device__ float g_mm [ML*DM];
__device__ float g_m1 [ML*DM];
__device__ float g_u  [ML*2*DM];
__device__ float g_z  [ML*DM];
__device__ float g_WqT[DM*DM];
__device__ float g_WkT[DM*DM];
__device__ float g_WvT[DM*DM];
__device__ float g_WmT[DM*DM];
__device__ float g_W1T[2*DM*2*DM];
__device__ float g_W2T[DM*2*DM];

__device__ __forceinline__ void mma_f16(float c[4], const unsigned a[4], const unsigned b[2]) {
    asm("mma.sync.aligned.m16n8k16.row.col.f32.f16.f16.f32 "
        "{%0,%1,%2,%3}, {%4,%5,%6,%7}, {%8,%9}, {%0,%1,%2,%3};"
        : "+f"(c[0]), "+f"(c[1]), "+f"(c[2]), "+f"(c[3])
        : "r"(a[0]), "r"(a[1]), "r"(a[2]), "r"(a[3]), "r"(b[0]), "r"(b[1]));
}

// ---------------------------------------------------------------------------
// fp16 tensor-core GEMM (fp32 accumulate): C[M,N] = A[M,K] @ B'[N,K]^T  (NT)
// 128x128 CTA tile, BK=32 halves, double-buffered smem, 256 threads = 8 warps
// as 4(m) x 2(n); warp tile 32x64 via m16n8k16 fragments.
// MODE 0: plain   MODE 1: dist = sqrt(max(e0[m]+e1[n]-2*acc, 0))
// MODE 2: A = virtual concat [A | A1] along K (each half lda=512), relu
// Batched via blockIdx.z with element strides sA/sB/sC (0 = shared operand).
// ---------------------------------------------------------------------------
template<int MODE>
__global__ __launch_bounds__(256)
void hgemm_k(const float* __restrict__ A, const float* __restrict__ A1,
             const float* __restrict__ B, float* __restrict__ C,
             int K, int lda, int ldb, int ldc,
             long sA, long sB, long sC,
             const float* __restrict__ e0, const float* __restrict__ e1,
             int se0, int se1)
{
    __shared__ __half As[2][128][PADK];
    __shared__ __half Bs[2][128][PADK];

    const int z = blockIdx.z;
    A += (long)z * sA;
    if (MODE == 2) A1 += (long)z * sA;
    B += (long)z * sB;
    C += (long)z * sC;
    const float* E0 = (MODE == 1) ? (e0 + (long)z * se0) : nullptr;
    const float* E1 = (MODE == 1) ? (e1 + (long)z * se1) : nullptr;

    const int t  = threadIdx.x;
    const int m0 = blockIdx.y * 128;
    const int n0 = blockIdx.x * 128;

    const int warpId = t >> 5;
    const int lane   = t & 31;
    const int mb     = (warpId >> 1) * 32;   // 0,32,64,96
    const int nb     = (warpId & 1) * 64;    // 0,64
    const int gq     = lane >> 2;            // 0..7
    const int tg     = lane & 3;             // 0..3

    // staging map: tile = 128 rows x 32 floats = 1024 float4 chunks.
    // thread t handles chunks t + i*256 (i=0..3): row = (t>>3) + i*32, col4 = (t&7)*4
    const int srow = t >> 3;
    const int sc4  = (t & 7) * 4;

    float acc[2][8][4];
#pragma unroll
    for (int i = 0; i < 2; i++)
#pragma unroll
        for (int j = 0; j < 8; j++)
#pragma unroll
            for (int r = 0; r < 4; r++) acc[i][j][r] = 0.f;

    // ---- prologue: stage k-chunk 0 into buffer 0
    {
#pragma unroll
        for (int i = 0; i < 4; i++) {
            const int row = srow + i * 32;
            float4 av = *reinterpret_cast<const float4*>(A + (long)(m0 + row) * lda + sc4);
            float4 bv = *reinterpret_cast<const float4*>(B + (long)(n0 + row) * ldb + sc4);
            *reinterpret_cast<__half2*>(&As[0][row][sc4])     = __floats2half2_rn(av.x, av.y);
            *reinterpret_cast<__half2*>(&As[0][row][sc4 + 2]) = __floats2half2_rn(av.z, av.w);
            *reinterpret_cast<__half2*>(&Bs[0][row][sc4])     = __floats2half2_rn(bv.x, bv.y);
            *reinterpret_cast<__half2*>(&Bs[0][row][sc4 + 2]) = __floats2half2_rn(bv.z, bv.w);
        }
    }
    __syncthreads();

    int buf = 0;
    const int NKT = K / BKH;
    for (int kt = 0; kt < NKT; kt++) {
        const bool last = (kt == NKT - 1);
        float4 av[4], bv[4];
        if (!last) {
            const int kn = (kt + 1) * BKH;
            const float* Asrc = A; int kk0 = kn;
            if (MODE == 2 && kn >= DM) { Asrc = A1; kk0 = kn - DM; }
#pragma unroll
            for (int i = 0; i < 4; i++) {
                const int row = srow + i * 32;
                av[i] = *reinterpret_cast<const float4*>(Asrc + (long)(m0 + row) * lda + kk0 + sc4);
                bv[i] = *reinterpret_cast<const float4*>(B + (long)(n0 + row) * ldb + kn + sc4);
            }
        }

        // ---- compute: two k16 steps on current buffer
#pragma unroll
        for (int ks = 0; ks < BKH; ks += 16) {
            unsigned a[2][4], b[8][2];
#pragma unroll
            for (int i = 0; i < 2; i++) {
                const int row = mb + i * 16 + gq;
                a[i][0] = *reinterpret_cast<const unsigned*>(&As[buf][row    ][ks + 2 * tg    ]);
                a[i][1] = *reinterpret_cast<const unsigned*>(&As[buf][row + 8][ks + 2 * tg    ]);
                a[i][2] = *reinterpret_cast<const unsigned*>(&As[buf][row    ][ks + 2 * tg + 8]);
                a[i][3] = *reinterpret_cast<const unsigned*>(&As[buf][row + 8][ks + 2 * tg + 8]);
            }
#pragma unroll
            for (int j = 0; j < 8; j++) {
                const int n = nb + j * 8 + gq;
                b[j][0] = *reinterpret_cast<const unsigned*>(&Bs[buf][n][ks + 2 * tg    ]);
                b[j][1] = *reinterpret_cast<const unsigned*>(&Bs[buf][n][ks + 2 * tg + 8]);
            }
#pragma unroll
            for (int i = 0; i < 2; i++)
#pragma unroll
                for (int j = 0; j < 8; j++)
                    mma_f16(acc[i][j], a[i], b[j]);
        }

        if (!last) {
            const int nx = buf ^ 1;
#pragma unroll
            for (int i = 0; i < 4; i++) {
                const int row = srow + i * 32;
                *reinterpret_cast<__half2*>(&As[nx][row][sc4])     = __floats2half2_rn(av[i].x, av[i].y);
                *reinterpret_cast<__half2*>(&As[nx][row][sc4 + 2]) = __floats2half2_rn(av[i].z, av[i].w);
                *reinterpret_cast<__half2*>(&Bs[nx][row][sc4])     = __floats2half2_rn(bv[i].x, bv[i].y);
                *reinterpret_cast<__half2*>(&Bs[nx][row][sc4 + 2]) = __floats2half2_rn(bv[i].z, bv[i].w);
            }
            __syncthreads();
            buf ^= 1;
        }
    }

    // ---- epilogue (C fragment: c0,c1 = rows gq / cols 2tg..+1; c2,c3 = rows gq+8)
#pragma unroll
    for (int i = 0; i < 2; i++) {
        const int row0 = m0 + mb + i * 16 + gq;
        const int row1 = row0 + 8;
#pragma unroll
        for (int j = 0; j < 8; j++) {
            const int col0 = n0 + nb + j * 8 + tg * 2;
            float v00 = acc[i][j][0], v01 = acc[i][j][1];
            float v10 = acc[i][j][2], v11 = acc[i][j][3];
            if (MODE == 1) {
                const float e00 = E0[row0], e01 = E0[row1];
                const float f0 = E1[col0], f1 = E1[col0 + 1];
                v00 = sqrtf(fmaxf(e00 + f0 - 2.f * v00, 0.f));
                v01 = sqrtf(fmaxf(e00 + f1 - 2.f * v01, 0.f));
                v10 = sqrtf(fmaxf(e01 + f0 - 2.f * v10, 0.f));
                v11 = sqrtf(fmaxf(e01 + f1 - 2.f * v11, 0.f));
            }
            if (MODE == 2) {
                v00 = fmaxf(v00, 0.f); v01 = fmaxf(v01, 0.f);
                v10 = fmaxf(v10, 0.f); v11 = fmaxf(v11, 0.f);
            }
            *reinterpret_cast<float2*>(C + (long)row0 * ldc + col0) = make_float2(v00, v01);
            *reinterpret_cast<float2*>(C + (long)row1 * ldc + col0) = make_float2(v10, v11);
        }
    }
}

// ---------------------------------------------------------------------------
// Tiled transpose: in [R,C] -> out [C,R], batched by blockIdx.z
// ---------------------------------------------------------------------------
__global__ __launch_bounds__(256)
void transpose_k(const float* __restrict__ in, float* __restrict__ outp, int R, int C)
{
    __shared__ float tile[32][33];
    const long zb = (long)blockIdx.z * (long)R * C;
    const int c0 = blockIdx.x * 32, r0 = blockIdx.y * 32;
    const int tx = threadIdx.x & 31, ty = threadIdx.x >> 5;
#pragma unroll
    for (int i = 0; i < 32; i += 8)
        tile[ty + i][tx] = in[zb + (long)(r0 + ty + i) * C + c0 + tx];
    __syncthreads();
#pragma unroll
    for (int i = 0; i < 32; i += 8)
        outp[zb + (long)(c0 + ty + i) * R + r0 + tx] = tile[tx][ty + i];
}

// Row squared-norms: one warp per row, cols = 512
__global__ __launch_bounds__(256)
void rownorm_k(const float* __restrict__ X, float* __restrict__ out, int cols)
{
    const int row  = blockIdx.x * 8 + (threadIdx.x >> 5);
    const int lane = threadIdx.x & 31;
    const float* p = X + (long)row * cols;
    float s = 0.f;
    for (int c = lane; c < cols; c += 32) { float v = p[c]; s = fmaf(v, v, s); }
#pragma unroll
    for (int o = 16; o; o >>= 1) s += __shfl_xor_sync(0xffffffffu, s, o);
    if (lane == 0) out[row] = s;
}

// Softmax over rows of 4096 (in-place), one block per row
__global__ __launch_bounds__(256)
void softmax_k(float* __restrict__ sc)
{
    float* p = sc + (long)blockIdx.x * 4096;
    const int t = threadIdx.x;
    float vals[16];
    float mx = -1e30f;
#pragma unroll
    for (int i = 0; i < 16; i++) { vals[i] = p[t + i * 256]; mx = fmaxf(mx, vals[i]); }
    __shared__ float red[256];
    red[t] = mx; __syncthreads();
    for (int o = 128; o; o >>= 1) { if (t < o) red[t] = fmaxf(red[t], red[t + o]); __syncthreads(); }
    mx = red[0]; __syncthreads();
    float s = 0.f;
#pragma unroll
    for (int i = 0; i < 16; i++) { vals[i] = __expf(vals[i] - mx); s += vals[i]; }
    red[t] = s; __syncthreads();
    for (int o = 128; o; o >>= 1) { if (t < o) red[t] += red[t + o]; __syncthreads(); }
    const float inv = 1.f / red[0];
#pragma unroll
    for (int i = 0; i < 16; i++) p[t + i * 256] = vals[i] * inv;
}

// LayerNorm over rows of 512; optional residual add. One block per row.
__global__ __launch_bounds__(256)
void ln_k(const float* __restrict__ X, const float* __restrict__ g,
          const float* __restrict__ b, const float* __restrict__ res,
          float* __restrict__ out)
{
    const long row = blockIdx.x;
    const float* p = X + row * 512;
    const int t = threadIdx.x;
    float v0 = p[t], v1 = p[t + 256];
    __shared__ float red[256];
    red[t] = v0 + v1; __syncthreads();
    for (int o = 128; o; o >>= 1) { if (t < o) red[t] += red[t + o]; __syncthreads(); }
    const float mu = red[0] * (1.f / 512.f);
    __syncthreads();
    const float d0 = v0 - mu, d1 = v1 - mu;
    red[t] = d0 * d0 + d1 * d1; __syncthreads();
    for (int o = 128; o; o >>= 1) { if (t < o) red[t] += red[t + o]; __syncthreads(); }
    const float rs = rsqrtf(red[0] * (1.f / 512.f) + 1e-5f);
    float o0 = d0 * rs * g[t]       + b[t];
    float o1 = d1 * rs * g[t + 256] + b[t + 256];
    if (res) { o0 += res[row * 512 + t]; o1 += res[row * 512 + t + 256]; }
    out[row * 512 + t]       = o0;
    out[row * 512 + t + 256] = o1;
}

template <typename T>
static float* sym(T& s) { void* p = nullptr; cudaGetSymbolAddress(&p, s); return (float*)p; }

extern "C" void kernel_launch(void* const* d_in, const int* in_sizes, int n_in,
                              void* d_out, int out_size)
{
    const float* x   = (const float*)d_in[0];
    const float* src = (const float*)d_in[1];
    const float* Wq  = (const float*)d_in[2];
    const float* Wk  = (const float*)d_in[3];
    const float* Wv  = (const float*)d_in[4];
    const float* Wm  = (const float*)d_in[5];
    const float* W1  = (const float*)d_in[6];
    const float* W2  = (const float*)d_in[7];
    const float* g1  = (const float*)d_in[8];
    const float* b1  = (const float*)d_in[9];
    const float* g2  = (const float*)d_in[10];
    const float* b2  = (const float*)d_in[11];
    float* out = (float*)d_out;

    float *q  = sym(g_q),  *k  = sym(g_k),  *v  = sym(g_v),  *vT = sym(g_vT);
    float *q2 = sym(g_q2), *k2 = sym(g_k2), *sc = sym(g_sc);
    float *ms = sym(g_ms), *mm = sym(g_mm), *m1 = sym(g_m1);
    float *u  = sym(g_u),  *zz = sym(g_z);
    float *wqT = sym(g_WqT), *wkT = sym(g_WkT), *wvT = sym(g_WvT);
    float *wmT = sym(g_WmT), *w1T = sym(g_W1T), *w2T = sym(g_W2T);

    // 0: weight transposes (all GEMMs run NT with K-major B' = W^T)
    transpose_k<<<dim3(DM/32,   DM/32,   1), 256>>>(Wq, wqT, DM,   DM);
    transpose_k<<<dim3(DM/32,   DM/32,   1), 256>>>(Wk, wkT, DM,   DM);
    transpose_k<<<dim3(DM/32,   DM/32,   1), 256>>>(Wv, wvT, DM,   DM);
    transpose_k<<<dim3(DM/32,   DM/32,   1), 256>>>(Wm, wmT, DM,   DM);
    transpose_k<<<dim3(2*DM/32, 2*DM/32, 1), 256>>>(W1, w1T, 2*DM, 2*DM);
    transpose_k<<<dim3(DM/32,   2*DM/32, 1), 256>>>(W2, w2T, 2*DM, DM);

    // 1-3: q/k/v projections (flattened over batch)
    hgemm_k<0><<<dim3(DM/128, ML/128, 1), 256>>>(x,   nullptr, wqT, q, DM, DM, DM, DM, 0, 0, 0, nullptr, nullptr, 0, 0);
    hgemm_k<0><<<dim3(DM/128, MS/128, 1), 256>>>(src, nullptr, wkT, k, DM, DM, DM, DM, 0, 0, 0, nullptr, nullptr, 0, 0);
    hgemm_k<0><<<dim3(DM/128, MS/128, 1), 256>>>(src, nullptr, wvT, v, DM, DM, DM, DM, 0, 0, 0, nullptr, nullptr, 0, 0);

    // v -> vT (per batch [SK,DM] -> [DM,SK]) so attn@v is NT too
    transpose_k<<<dim3(DM/32, SK/32, NB), 256>>>(v, vT, SK, DM);

    // 4-5: squared row norms (fp32 exact)
    rownorm_k<<<ML / 8, 256>>>(q, q2, DM);
    rownorm_k<<<MS / 8, 256>>>(k, k2, DM);

    // 6: dist = sqrt(max(q2 + k2 - 2 q.k, 0))  (batched NT, fused epilogue)
    hgemm_k<1><<<dim3(SK/128, LQ/128, NB), 256>>>(q, nullptr, k, sc,
        DM, DM, DM, SK, (long)LQ*DM, (long)SK*DM, (long)LQ*SK, q2, k2, LQ, SK);

    // 7: softmax over S (in-place)
    softmax_k<<<ML, 256>>>(sc);

    // 8: message = attn @ v  (A = attn [LQ,SK], B' = vT [DM,SK])
    hgemm_k<0><<<dim3(DM/128, LQ/128, NB), 256>>>(sc, nullptr, vT, ms,
        SK, SK, SK, DM, (long)LQ*SK, (long)DM*SK, (long)LQ*DM, nullptr, nullptr, 0, 0);

    // 9: message @ Wm
    hgemm_k<0><<<dim3(DM/128, ML/128, 1), 256>>>(ms, nullptr, wmT, mm, DM, DM, DM, DM, 0, 0, 0, nullptr, nullptr, 0, 0);

    // 10: layernorm1
    ln_k<<<ML, 256>>>(mm, g1, b1, nullptr, m1);

    // 11: u = relu([x | m1] @ W1)  (fused concat + relu)
    hgemm_k<2><<<dim3(2*DM/128, ML/128, 1), 256>>>(x, m1, w1T, u, 2*DM, DM, 2*DM, 2*DM, 0, 0, 0, nullptr, nullptr, 0, 0);

    // 12: z = u @ W2
    hgemm_k<0><<<dim3(DM/128, ML/128, 1), 256>>>(u, nullptr, w2T, zz, 2*DM, 2*DM, 2*DM, DM, 0, 0, 0, nullptr, nullptr, 0, 0);

    // 13: out = x + layernorm2(z)
    ln_k<<<ML, 256>>>(zz, g2, b2, x, out);
}

// round 9
// speedup vs baseline: 5.3830x; 1.4870x over previous
#include <cuda_runtime.h>
#include <cuda_fp16.h>
#include <math.h>
#include <stdint.h>

// Problem dims
#define NB 8
#define LQ 1024
#define SK 4096
#define DM 512
#define ML (NB*LQ)   // 8192
#define MS (NB*SK)   // 32768
#define BKH 32       // k-chunk (halves) per buffer = two k16 MMA steps
#define PADK 40      // padded row stride in halves (conflict-free fragment LDS)

// ---------------------------------------------------------------------------
// Scratch (device globals: no allocations allowed)
// ---------------------------------------------------------------------------
__device__ __half g_xh [ML*DM];
__device__ __half g_sh [MS*DM];
__device__ __half g_q  [ML*DM];
__device__ __half g_k  [MS*DM];
__device__ __half g_vT [(size_t)NB*DM*SK];
__device__ float  g_q2 [ML];
__device__ float  g_k2 [MS];
__device__ __half g_sc [(size_t)NB*LQ*SK];
__device__ __half g_ms [ML*DM];
__device__ float  g_mm [ML*DM];
__device__ __half g_m1 [ML*DM];
__device__ __half g_u  [ML*2*DM];
__device__ float  g_z  [ML*DM];
__device__ __half g_WqT[DM*DM];
__device__ __half g_WkT[DM*DM];
__device__ __half g_WvT[DM*DM];
__device__ __half g_WmT[DM*DM];
__device__ __half g_W1T[2*DM*2*DM];
__device__ __half g_W2T[DM*2*DM];

__device__ __forceinline__ uint32_t s2u(const void* p) {
    uint32_t a;
    asm("{ .reg .u64 t; cvta.to.shared.u64 t, %1; cvt.u32.u64 %0, t; }" : "=r"(a) : "l"(p));
    return a;
}

__device__ __forceinline__ void mma_f16(float c[4], const unsigned a[4], const unsigned b[2]) {
    asm("mma.sync.aligned.m16n8k16.row.col.f32.f16.f16.f32 "
        "{%0,%1,%2,%3}, {%4,%5,%6,%7}, {%8,%9}, {%0,%1,%2,%3};"
        : "+f"(c[0]), "+f"(c[1]), "+f"(c[2]), "+f"(c[3])
        : "r"(a[0]), "r"(a[1]), "r"(a[2]), "r"(a[3]), "r"(b[0]), "r"(b[1]));
}

__device__ __forceinline__ void cp16(uint32_t dst, const void* src) {
    asm volatile("cp.async.cg.shared.global [%0], [%1], 16;" :: "r"(dst), "l"(src));
}

// ---------------------------------------------------------------------------
// fp16 tensor-core GEMM (fp32 accumulate): C[M,N] = A[M,K] @ B'[N,K]^T  (NT)
// fp16 operands in gmem, cp.async double-buffered staging, 256 threads = 8
// warps (4m x 2n), warp tile 32x64 via m16n8k16.
// MODE 0: plain   MODE 1: dist = sqrt(max(e0[m]+e1[n]-2*acc, 0))
// MODE 2: A = virtual concat [A | A1] along K (each half lda), relu epilogue
// OT = float or __half output.
// ---------------------------------------------------------------------------
template<int MODE, typename OT>
__global__ __launch_bounds__(256)
void hgemm_k(const __half* __restrict__ A, const __half* __restrict__ A1,
             const __half* __restrict__ B, OT* __restrict__ C,
             int K, int lda, int ldb, int ldc,
             long sA, long sB, long sC,
             const float* __restrict__ e0, const float* __restrict__ e1,
             int se0, int se1)
{
    __shared__ __half As[2][128][PADK];
    __shared__ __half Bs[2][128][PADK];

    const int z = blockIdx.z;
    A += (long)z * sA;
    if (MODE == 2) A1 += (long)z * sA;
    B += (long)z * sB;
    C += (long)z * sC;
    const float* E0 = (MODE == 1) ? (e0 + (long)z * se0) : nullptr;
    const float* E1 = (MODE == 1) ? (e1 + (long)z * se1) : nullptr;

    const int t  = threadIdx.x;
    const int m0 = blockIdx.y * 128;
    const int n0 = blockIdx.x * 128;

    const int warpId = t >> 5;
    const int lane   = t & 31;
    const int mb     = (warpId >> 1) * 32;   // 0,32,64,96
    const int nb     = (warpId & 1) * 64;    // 0,64
    const int gq     = lane >> 2;            // 0..7
    const int tg     = lane & 3;             // 0..3

    // staging: tile = 128 rows x 32 halves = 128 rows x 4 x 16B chunks.
    // 512 chunks/operand, 256 threads -> 2 chunks each (c = t, t+256):
    //   row = c>>2, chunk = c&3 (8 halves)
    const int r0s = t >> 2,          c0s = (t & 3) * 8;
    const int r1s = (t + 256) >> 2;  // chunk index same (c&3 identical)

    float acc[2][8][4];
#pragma unroll
    for (int i = 0; i < 2; i++)
#pragma unroll
        for (int j = 0; j < 8; j++)
#pragma unroll
            for (int r = 0; r < 4; r++) acc[i][j][r] = 0.f;

    const int NKT = K / BKH;

    // stage k-chunk kt into buffer b
    auto stage = [&](int kt, int b) {
        const int k0 = kt * BKH;
        const __half* Asrc = A; int kk0 = k0;
        if (MODE == 2 && k0 >= DM) { Asrc = A1; kk0 = k0 - DM; }
        cp16(s2u(&As[b][r0s][c0s]), Asrc + (long)(m0 + r0s) * lda + kk0 + c0s);
        cp16(s2u(&As[b][r1s][c0s]), Asrc + (long)(m0 + r1s) * lda + kk0 + c0s);
        cp16(s2u(&Bs[b][r0s][c0s]), B + (long)(n0 + r0s) * ldb + k0 + c0s);
        cp16(s2u(&Bs[b][r1s][c0s]), B + (long)(n0 + r1s) * ldb + k0 + c0s);
        asm volatile("cp.async.commit_group;");
    };

    stage(0, 0);

    int buf = 0;
    for (int kt = 0; kt < NKT; kt++) {
        asm volatile("cp.async.wait_group 0;");
        __syncthreads();
        if (kt + 1 < NKT) stage(kt + 1, buf ^ 1);

        // ---- compute: two k16 steps on current buffer
#pragma unroll
        for (int ks = 0; ks < BKH; ks += 16) {
            unsigned a[2][4], b[8][2];
#pragma unroll
            for (int i = 0; i < 2; i++) {
                const int row = mb + i * 16 + gq;
                a[i][0] = *reinterpret_cast<const unsigned*>(&As[buf][row    ][ks + 2 * tg    ]);
                a[i][1] = *reinterpret_cast<const unsigned*>(&As[buf][row + 8][ks + 2 * tg    ]);
                a[i][2] = *reinterpret_cast<const unsigned*>(&As[buf][row    ][ks + 2 * tg + 8]);
                a[i][3] = *reinterpret_cast<const unsigned*>(&As[buf][row + 8][ks + 2 * tg + 8]);
            }
#pragma unroll
            for (int j = 0; j < 8; j++) {
                const int n = nb + j * 8 + gq;
                b[j][0] = *reinterpret_cast<const unsigned*>(&Bs[buf][n][ks + 2 * tg    ]);
                b[j][1] = *reinterpret_cast<const unsigned*>(&Bs[buf][n][ks + 2 * tg + 8]);
            }
#pragma unroll
            for (int i = 0; i < 2; i++)
#pragma unroll
                for (int j = 0; j < 8; j++)
                    mma_f16(acc[i][j], a[i], b[j]);
        }
        buf ^= 1;
    }

    // ---- epilogue (fragment: c0,c1 = row gq, cols 2tg..+1; c2,c3 = row gq+8)
#pragma unroll
    for (int i = 0; i < 2; i++) {
        const int row0 = m0 + mb + i * 16 + gq;
        const int row1 = row0 + 8;
#pragma unroll
        for (int j = 0; j < 8; j++) {
            const int col0 = n0 + nb + j * 8 + tg * 2;
            float v00 = acc[i][j][0], v01 = acc[i][j][1];
            float v10 = acc[i][j][2], v11 = acc[i][j][3];
            if (MODE == 1) {
                const float e00 = E0[row0], e01 = E0[row1];
                const float f0 = E1[col0], f1 = E1[col0 + 1];
                v00 = sqrtf(fmaxf(e00 + f0 - 2.f * v00, 0.f));
                v01 = sqrtf(fmaxf(e00 + f1 - 2.f * v01, 0.f));
                v10 = sqrtf(fmaxf(e01 + f0 - 2.f * v10, 0.f));
                v11 = sqrtf(fmaxf(e01 + f1 - 2.f * v11, 0.f));
            }
            if (MODE == 2) {
                v00 = fmaxf(v00, 0.f); v01 = fmaxf(v01, 0.f);
                v10 = fmaxf(v10, 0.f); v11 = fmaxf(v11, 0.f);
            }
            if constexpr (sizeof(OT) == 2) {
                *reinterpret_cast<__half2*>((__half*)C + (long)row0 * ldc + col0) = __floats2half2_rn(v00, v01);
                *reinterpret_cast<__half2*>((__half*)C + (long)row1 * ldc + col0) = __floats2half2_rn(v10, v11);
            } else {
                *reinterpret_cast<float2*>((float*)C + (long)row0 * ldc + col0) = make_float2(v00, v01);
                *reinterpret_cast<float2*>((float*)C + (long)row1 * ldc + col0) = make_float2(v10, v11);
            }
        }
    }
}

// ---------------------------------------------------------------------------
// fp32 -> fp16 elementwise (n multiple of 1024)
// ---------------------------------------------------------------------------
__global__ __launch_bounds__(256)
void f2h_k(const float* __restrict__ in, __half* __restrict__ outp)
{
    const int i = (blockIdx.x * 256 + threadIdx.x) * 4;
    float4 v = *reinterpret_cast<const float4*>(in + i);
    *reinterpret_cast<__half2*>(outp + i)     = __floats2half2_rn(v.x, v.y);
    *reinterpret_cast<__half2*>(outp + i + 2) = __floats2half2_rn(v.z, v.w);
}

// ---------------------------------------------------------------------------
// Tiled transpose fp32 -> fp16: in [R,C] -> out [C,R]
// ---------------------------------------------------------------------------
__global__ __launch_bounds__(256)
void transpose_h(const float* __restrict__ in, __half* __restrict__ outp, int R, int C)
{
    __shared__ float tile[32][33];
    const int c0 = blockIdx.x * 32, r0 = blockIdx.y * 32;
    const int tx = threadIdx.x & 31, ty = threadIdx.x >> 5;
#pragma unroll
    for (int i = 0; i < 32; i += 8)
        tile[ty + i][tx] = in[(long)(r0 + ty + i) * C + c0 + tx];
    __syncthreads();
#pragma unroll
    for (int i = 0; i < 32; i += 8)
        outp[(long)(c0 + ty + i) * R + r0 + tx] = __float2half_rn(tile[tx][ty + i]);
}

// Row squared-norms over fp16 rows of 512, fp32 accumulate: one warp per row
__global__ __launch_bounds__(256)
void rownorm_h(const __half* __restrict__ X, float* __restrict__ out)
{
    const int row  = blockIdx.x * 8 + (threadIdx.x >> 5);
    const int lane = threadIdx.x & 31;
    const __half2* p = reinterpret_cast<const __half2*>(X + (long)row * DM);
    float s = 0.f;
#pragma unroll
    for (int c = 0; c < 8; c++) {
        float2 v = __half22float2(p[lane + c * 32]);
        s = fmaf(v.x, v.x, fmaf(v.y, v.y, s));
    }
#pragma unroll
    for (int o = 16; o; o >>= 1) s += __shfl_xor_sync(0xffffffffu, s, o);
    if (lane == 0) out[row] = s;
}

// Softmax over fp16 rows of 4096 (in-place), one block per row
__global__ __launch_bounds__(256)
void softmax_h(__half* __restrict__ sc)
{
    __half2* p = reinterpret_cast<__half2*>(sc + (long)blockIdx.x * 4096);
    const int t = threadIdx.x;
    float2 vals[8];
    float mx = -1e30f;
#pragma unroll
    for (int i = 0; i < 8; i++) {
        vals[i] = __half22float2(p[t + i * 256]);
        mx = fmaxf(mx, fmaxf(vals[i].x, vals[i].y));
    }
    __shared__ float red[256];
    red[t] = mx; __syncthreads();
    for (int o = 128; o; o >>= 1) { if (t < o) red[t] = fmaxf(red[t], red[t + o]); __syncthreads(); }
    mx = red[0]; __syncthreads();
    float s = 0.f;
#pragma unroll
    for (int i = 0; i < 8; i++) {
        vals[i].x = __expf(vals[i].x - mx);
        vals[i].y = __expf(vals[i].y - mx);
        s += vals[i].x + vals[i].y;
    }
    red[t] = s; __syncthreads();
    for (int o = 128; o; o >>= 1) { if (t < o) red[t] += red[t + o]; __syncthreads(); }
    const float inv = 1.f / red[0];
#pragma unroll
    for (int i = 0; i < 8; i++)
        p[t + i * 256] = __floats2half2_rn(vals[i].x * inv, vals[i].y * inv);
}

// LayerNorm over fp32 rows of 512; optional fp32 residual; OT output.
template<typename OT>
__global__ __launch_bounds__(256)
void ln_k(const float* __restrict__ X, const float* __restrict__ g,
          const float* __restrict__ b, const float* __restrict__ res,
          OT* __restrict__ out)
{
    const long row = blockIdx.x;
    const float* p = X + row * 512;
    const int t = threadIdx.x;
    float v0 = p[t], v1 = p[t + 256];
    __shared__ float red[256];
    red[t] = v0 + v1; __syncthreads();
    for (int o = 128; o; o >>= 1) { if (t < o) red[t] += red[t + o]; __syncthreads(); }
    const float mu = red[0] * (1.f / 512.f);
    __syncthreads();
    const float d0 = v0 - mu, d1 = v1 - mu;
    red[t] = d0 * d0 + d1 * d1; __syncthreads();
    for (int o = 128; o; o >>= 1) { if (t < o) red[t] += red[t + o]; __syncthreads(); }
    const float rs = rsqrtf(red[0] * (1.f / 512.f) + 1e-5f);
    float o0 = d0 * rs * g[t]       + b[t];
    float o1 = d1 * rs * g[t + 256] + b[t + 256];
    if (res) { o0 += res[row * 512 + t]; o1 += res[row * 512 + t + 256]; }
    if constexpr (sizeof(OT) == 2) {
        out[row * 512 + t]       = __float2half_rn(o0);
        out[row * 512 + t + 256] = __float2half_rn(o1);
    } else {
        out[row * 512 + t]       = o0;
        out[row * 512 + t + 256] = o1;
    }
}

template <typename P, typename T>
static P sym(T& s) { void* p = nullptr; cudaGetSymbolAddress(&p, s); return (P)p; }

extern "C" void kernel_launch(void* const* d_in, const int* in_sizes, int n_in,
                              void* d_out, int out_size)
{
    const float* x   = (const float*)d_in[0];
    const float* src = (const float*)d_in[1];
    const float* Wq  = (const float*)d_in[2];
    const float* Wk  = (const float*)d_in[3];
    const float* Wv  = (const float*)d_in[4];
    const float* Wm  = (const float*)d_in[5];
    const float* W1  = (const float*)d_in[6];
    const float* W2  = (const float*)d_in[7];
    const float* g1  = (const float*)d_in[8];
    const float* b1  = (const float*)d_in[9];
    const float* g2  = (const float*)d_in[10];
    const float* b2  = (const float*)d_in[11];
    float* out = (float*)d_out;

    __half *xh = sym<__half*>(g_xh), *sh = sym<__half*>(g_sh);
    __half *q  = sym<__half*>(g_q),  *k  = sym<__half*>(g_k),  *vT = sym<__half*>(g_vT);
    __half *sc = sym<__half*>(g_sc), *ms = sym<__half*>(g_ms), *m1 = sym<__half*>(g_m1);
    __half *u  = sym<__half*>(g_u);
    float  *q2 = sym<float*>(g_q2),  *k2 = sym<float*>(g_k2);
    float  *mm = sym<float*>(g_mm),  *zz = sym<float*>(g_z);
    __half *wqT = sym<__half*>(g_WqT), *wkT = sym<__half*>(g_WkT), *wvT = sym<__half*>(g_WvT);
    __half *wmT = sym<__half*>(g_WmT), *w1T = sym<__half*>(g_W1T), *w2T = sym<__half*>(g_W2T);

    // 0a: input conversions fp32 -> fp16
    f2h_k<<<ML*DM/1024, 256>>>(x,   xh);
    f2h_k<<<MS*DM/1024, 256>>>(src, sh);

    // 0b: weight transposes -> fp16 (all GEMMs run NT with K-major B' = W^T)
    transpose_h<<<dim3(DM/32,   DM/32),   256>>>(Wq, wqT, DM,   DM);
    transpose_h<<<dim3(DM/32,   DM/32),   256>>>(Wk, wkT, DM,   DM);
    transpose_h<<<dim3(DM/32,   DM/32),   256>>>(Wv, wvT, DM,   DM);
    transpose_h<<<dim3(DM/32,   DM/32),   256>>>(Wm, wmT, DM,   DM);
    transpose_h<<<dim3(2*DM/32, 2*DM/32), 256>>>(W1, w1T, 2*DM, 2*DM);
    transpose_h<<<dim3(DM/32,   2*DM/32), 256>>>(W2, w2T, 2*DM, DM);

    // 1-2: q/k projections (flattened over batch)
    hgemm_k<0, __half><<<dim3(DM/128, ML/128, 1), 256>>>(xh, nullptr, wqT, q, DM, DM, DM, DM, 0, 0, 0, nullptr, nullptr, 0, 0);
    hgemm_k<0, __half><<<dim3(DM/128, MS/128, 1), 256>>>(sh, nullptr, wkT, k, DM, DM, DM, DM, 0, 0, 0, nullptr, nullptr, 0, 0);

    // 3: vT = (src @ Wv)^T computed directly: C[d][s] = sum_k WvT[d][k]*src[s][k]
    hgemm_k<0, __half><<<dim3(SK/128, DM/128, NB), 256>>>(wvT, nullptr, sh, vT,
        DM, DM, DM, SK, 0, (long)SK*DM, (long)DM*SK, nullptr, nullptr, 0, 0);

    // 4-5: squared row norms (fp32 accumulate over the same fp16 values the MMA sees)
    rownorm_h<<<ML / 8, 256>>>(q, q2);
    rownorm_h<<<MS / 8, 256>>>(k, k2);

    // 6: dist = sqrt(max(q2 + k2 - 2 q.k, 0))  (batched NT, fused epilogue, fp16 out)
    hgemm_k<1, __half><<<dim3(SK/128, LQ/128, NB), 256>>>(q, nullptr, k, sc,
        DM, DM, DM, SK, (long)LQ*DM, (long)SK*DM, (long)LQ*SK, q2, k2, LQ, SK);

    // 7: softmax over S (in-place, fp16)
    softmax_h<<<ML, 256>>>(sc);

    // 8: message = attn @ v  (A = attn [LQ,SK], B' = vT [DM,SK])
    hgemm_k<0, __half><<<dim3(DM/128, LQ/128, NB), 256>>>(sc, nullptr, vT, ms,
        SK, SK, SK, DM, (long)LQ*SK, (long)DM*SK, (long)LQ*DM, nullptr, nullptr, 0, 0);

    // 9: mm = message @ Wm  (fp32 out -> layernorm)
    hgemm_k<0, float><<<dim3(DM/128, ML/128, 1), 256>>>(ms, nullptr, wmT, mm, DM, DM, DM, DM, 0, 0, 0, nullptr, nullptr, 0, 0);

    // 10: layernorm1 -> fp16
    ln_k<__half><<<ML, 256>>>(mm, g1, b1, nullptr, m1);

    // 11: u = relu([x | m1] @ W1)  (fused concat + relu, fp16 out)
    hgemm_k<2, __half><<<dim3(2*DM/128, ML/128, 1), 256>>>(xh, m1, w1T, u, 2*DM, DM, 2*DM, 2*DM, 0, 0, 0, nullptr, nullptr, 0, 0);

    // 12: z = u @ W2  (fp32 out -> layernorm)
    hgemm_k<0, float><<<dim3(DM/128, ML/128, 1), 256>>>(u, nullptr, w2T, zz, 2*DM, 2*DM, 2*DM, DM, 0, 0, 0, nullptr, nullptr, 0, 0);

    // 13: out = x + layernorm2(z)
    ln_k<float><<<ML, 256>>>(zz, g2, b2, x, out);
}

// round 10
// speedup vs baseline: 5.4771x; 1.0175x over previous
#include <cuda_runtime.h>
#include <cuda_fp16.h>
#include <math.h>
#include <stdint.h>

// Problem dims
#define NB 8
#define LQ 1024
#define SK 4096
#define DM 512
#define ML (NB*LQ)   // 8192
#define MS (NB*SK)   // 32768
#define BKH 32       // k-chunk (halves) per buffer = two k16 MMA steps
#define PADK 40      // padded row stride in halves (conflict-free LDS + LDSM)

// ---------------------------------------------------------------------------
// Scratch (device globals: no allocations allowed)
// ---------------------------------------------------------------------------
__device__ __half g_xh [ML*DM];
__device__ __half g_sh [MS*DM];
__device__ __half g_q  [ML*DM];
__device__ __half g_k  [MS*DM];
__device__ __half g_vT [(size_t)NB*DM*SK];
__device__ float  g_q2 [ML];
__device__ float  g_k2 [MS];
__device__ float  g_scf[(size_t)NB*LQ*SK];   // fp32 distances
__device__ __half g_sc [(size_t)NB*LQ*SK];   // fp16 attn weights
__device__ __half g_ms [ML*DM];
__device__ float  g_mm [ML*DM];
__device__ __half g_m1 [ML*DM];
__device__ __half g_u  [ML*2*DM];
__device__ float  g_z  [ML*DM];
__device__ __half g_WqT[DM*DM];
__device__ __half g_WkT[DM*DM];
__device__ __half g_WvT[DM*DM];
__device__ __half g_WmT[DM*DM];
__device__ __half g_W1T[2*DM*2*DM];
__device__ __half g_W2T[DM*2*DM];

__device__ __forceinline__ uint32_t s2u(const void* p) {
    uint32_t a;
    asm("{ .reg .u64 t; cvta.to.shared.u64 t, %1; cvt.u32.u64 %0, t; }" : "=r"(a) : "l"(p));
    return a;
}

__device__ __forceinline__ void mma_f16(float c[4], const unsigned a[4], const unsigned b[2]) {
    asm("mma.sync.aligned.m16n8k16.row.col.f32.f16.f16.f32 "
        "{%0,%1,%2,%3}, {%4,%5,%6,%7}, {%8,%9}, {%0,%1,%2,%3};"
        : "+f"(c[0]), "+f"(c[1]), "+f"(c[2]), "+f"(c[3])
        : "r"(a[0]), "r"(a[1]), "r"(a[2]), "r"(a[3]), "r"(b[0]), "r"(b[1]));
}

__device__ __forceinline__ void ldsm4(unsigned r[4], uint32_t addr) {
    asm volatile("ldmatrix.sync.aligned.m8n8.x4.shared.b16 {%0,%1,%2,%3}, [%4];"
        : "=r"(r[0]), "=r"(r[1]), "=r"(r[2]), "=r"(r[3]) : "r"(addr));
}

__device__ __forceinline__ void cp16(uint32_t dst, const void* src) {
    asm volatile("cp.async.cg.shared.global [%0], [%1], 16;" :: "r"(dst), "l"(src));
}

// ---------------------------------------------------------------------------
// fp16 tensor-core GEMM (fp32 accumulate): C[M,N] = A[M,K] @ B'[N,K]^T  (NT)
// fp16 operands in gmem, cp.async double-buffered staging, ldmatrix fragment
// loads, 256 threads = 8 warps (4m x 2n), warp tile 32x64 via m16n8k16.
// MODE 0: plain   MODE 1: dist = sqrt(max(e0[m]+e1[n]-2*acc, 0))
// MODE 2: A = virtual concat [A | A1] along K (each half lda), relu epilogue
// OT = float or __half output.
// ---------------------------------------------------------------------------
template<int MODE, typename OT>
__global__ __launch_bounds__(256)
void hgemm_k(const __half* __restrict__ A, const __half* __restrict__ A1,
             const __half* __restrict__ B, OT* __restrict__ C,
             int K, int lda, int ldb, int ldc,
             long sA, long sB, long sC,
             const float* __restrict__ e0, const float* __restrict__ e1,
             int se0, int se1)
{
    __shared__ __half As[2][128][PADK];
    __shared__ __half Bs[2][128][PADK];

    const int z = blockIdx.z;
    A += (long)z * sA;
    if (MODE == 2) A1 += (long)z * sA;
    B += (long)z * sB;
    C += (long)z * sC;
    const float* E0 = (MODE == 1) ? (e0 + (long)z * se0) : nullptr;
    const float* E1 = (MODE == 1) ? (e1 + (long)z * se1) : nullptr;

    const int t  = threadIdx.x;
    const int m0 = blockIdx.y * 128;
    const int n0 = blockIdx.x * 128;

    const int warpId = t >> 5;
    const int lane   = t & 31;
    const int mb     = (warpId >> 1) * 32;   // 0,32,64,96
    const int nb     = (warpId & 1) * 64;    // 0,64
    const int gq     = lane >> 2;            // 0..7
    const int tg     = lane & 3;             // 0..3

    // ldmatrix per-lane source rows/cols
    const int lrowA = lane & 15;                          // row within 16-row group
    const int kcolA = (lane >> 4) * 8;                    // k-chunk select
    const int lrowB = ((lane >> 4) << 3) + (lane & 7);    // row within n16 group
    const int kcolB = ((lane >> 3) & 1) * 8;              // k-chunk select

    // staging: tile = 128 rows x 32 halves; 512 16B-chunks/operand, 2 per thread
    const int r0s = t >> 2,          c0s = (t & 3) * 8;
    const int r1s = (t + 256) >> 2;

    float acc[2][8][4];
#pragma unroll
    for (int i = 0; i < 2; i++)
#pragma unroll
        for (int j = 0; j < 8; j++)
#pragma unroll
            for (int r = 0; r < 4; r++) acc[i][j][r] = 0.f;

    const int NKT = K / BKH;

    auto stage = [&](int kt, int b) {
        const int k0 = kt * BKH;
        const __half* Asrc = A; int kk0 = k0;
        if (MODE == 2 && k0 >= DM) { Asrc = A1; kk0 = k0 - DM; }
        cp16(s2u(&As[b][r0s][c0s]), Asrc + (long)(m0 + r0s) * lda + kk0 + c0s);
        cp16(s2u(&As[b][r1s][c0s]), Asrc + (long)(m0 + r1s) * lda + kk0 + c0s);
        cp16(s2u(&Bs[b][r0s][c0s]), B + (long)(n0 + r0s) * ldb + k0 + c0s);
        cp16(s2u(&Bs[b][r1s][c0s]), B + (long)(n0 + r1s) * ldb + k0 + c0s);
        asm volatile("cp.async.commit_group;");
    };

    stage(0, 0);

    int buf = 0;
    for (int kt = 0; kt < NKT; kt++) {
        asm volatile("cp.async.wait_group 0;");
        __syncthreads();
        if (kt + 1 < NKT) stage(kt + 1, buf ^ 1);

        const uint32_t baseA = s2u(&As[buf][0][0]);
        const uint32_t baseB = s2u(&Bs[buf][0][0]);

#pragma unroll
        for (int ks = 0; ks < BKH; ks += 16) {
            unsigned a[2][4], b[8][2];
#pragma unroll
            for (int i = 0; i < 2; i++)
                ldsm4(a[i], baseA + (uint32_t)((mb + i * 16 + lrowA) * PADK + ks + kcolA) * 2u);
#pragma unroll
            for (int j2 = 0; j2 < 4; j2++) {
                unsigned r[4];
                ldsm4(r, baseB + (uint32_t)((nb + j2 * 16 + lrowB) * PADK + ks + kcolB) * 2u);
                b[2*j2    ][0] = r[0]; b[2*j2    ][1] = r[1];
                b[2*j2 + 1][0] = r[2]; b[2*j2 + 1][1] = r[3];
            }
#pragma unroll
            for (int i = 0; i < 2; i++)
#pragma unroll
                for (int j = 0; j < 8; j++)
                    mma_f16(acc[i][j], a[i], b[j]);
        }
        buf ^= 1;
    }

    // ---- epilogue (fragment: c0,c1 = row gq, cols 2tg..+1; c2,c3 = row gq+8)
#pragma unroll
    for (int i = 0; i < 2; i++) {
        const int row0 = m0 + mb + i * 16 + gq;
        const int row1 = row0 + 8;
#pragma unroll
        for (int j = 0; j < 8; j++) {
            const int col0 = n0 + nb + j * 8 + tg * 2;
            float v00 = acc[i][j][0], v01 = acc[i][j][1];
            float v10 = acc[i][j][2], v11 = acc[i][j][3];
            if (MODE == 1) {
                const float e00 = E0[row0], e01 = E0[row1];
                const float f0 = E1[col0], f1 = E1[col0 + 1];
                v00 = sqrtf(fmaxf(e00 + f0 - 2.f * v00, 0.f));
                v01 = sqrtf(fmaxf(e00 + f1 - 2.f * v01, 0.f));
                v10 = sqrtf(fmaxf(e01 + f0 - 2.f * v10, 0.f));
                v11 = sqrtf(fmaxf(e01 + f1 - 2.f * v11, 0.f));
            }
            if (MODE == 2) {
                v00 = fmaxf(v00, 0.f); v01 = fmaxf(v01, 0.f);
                v10 = fmaxf(v10, 0.f); v11 = fmaxf(v11, 0.f);
            }
            if constexpr (sizeof(OT) == 2) {
                *reinterpret_cast<__half2*>((__half*)C + (long)row0 * ldc + col0) = __floats2half2_rn(v00, v01);
                *reinterpret_cast<__half2*>((__half*)C + (long)row1 * ldc + col0) = __floats2half2_rn(v10, v11);
            } else {
                *reinterpret_cast<float2*>((float*)C + (long)row0 * ldc + col0) = make_float2(v00, v01);
                *reinterpret_cast<float2*>((float*)C + (long)row1 * ldc + col0) = make_float2(v10, v11);
            }
        }
    }
}

// ---------------------------------------------------------------------------
// fp32 -> fp16 elementwise (n multiple of 1024)
// ---------------------------------------------------------------------------
__global__ __launch_bounds__(256)
void f2h_k(const float* __restrict__ in, __half* __restrict__ outp)
{
    const int i = (blockIdx.x * 256 + threadIdx.x) * 4;
    float4 v = *reinterpret_cast<const float4*>(in + i);
    *reinterpret_cast<__half2*>(outp + i)     = __floats2half2_rn(v.x, v.y);
    *reinterpret_cast<__half2*>(outp + i + 2) = __floats2half2_rn(v.z, v.w);
}

// ---------------------------------------------------------------------------
// Tiled transpose fp32 -> fp16: in [R,C] -> out [C,R]
// ---------------------------------------------------------------------------
__global__ __launch_bounds__(256)
void transpose_h(const float* __restrict__ in, __half* __restrict__ outp, int R, int C)
{
    __shared__ float tile[32][33];
    const int c0 = blockIdx.x * 32, r0 = blockIdx.y * 32;
    const int tx = threadIdx.x & 31, ty = threadIdx.x >> 5;
#pragma unroll
    for (int i = 0; i < 32; i += 8)
        tile[ty + i][tx] = in[(long)(r0 + ty + i) * C + c0 + tx];
    __syncthreads();
#pragma unroll
    for (int i = 0; i < 32; i += 8)
        outp[(long)(c0 + ty + i) * R + r0 + tx] = __float2half_rn(tile[tx][ty + i]);
}

// Row squared-norms over fp16 rows of 512, fp32 accumulate: one warp per row
__global__ __launch_bounds__(256)
void rownorm_h(const __half* __restrict__ X, float* __restrict__ out)
{
    const int row  = blockIdx.x * 8 + (threadIdx.x >> 5);
    const int lane = threadIdx.x & 31;
    const __half2* p = reinterpret_cast<const __half2*>(X + (long)row * DM);
    float s = 0.f;
#pragma unroll
    for (int c = 0; c < 8; c++) {
        float2 v = __half22float2(p[lane + c * 32]);
        s = fmaf(v.x, v.x, fmaf(v.y, v.y, s));
    }
#pragma unroll
    for (int o = 16; o; o >>= 1) s += __shfl_xor_sync(0xffffffffu, s, o);
    if (lane == 0) out[row] = s;
}

// Softmax over rows of 4096: read fp32 dist, write fp16 attn. One block/row.
__global__ __launch_bounds__(256)
void softmax_fh(const float* __restrict__ scf, __half* __restrict__ sc)
{
    const float* p = scf + (long)blockIdx.x * 4096;
    __half* o = sc + (long)blockIdx.x * 4096;
    const int t = threadIdx.x;
    float4 vals[4];
    float mx = -1e30f;
#pragma unroll
    for (int i = 0; i < 4; i++) {
        vals[i] = *reinterpret_cast<const float4*>(p + t * 16 + i * 4);
        mx = fmaxf(mx, fmaxf(fmaxf(vals[i].x, vals[i].y), fmaxf(vals[i].z, vals[i].w)));
    }
    __shared__ float red[256];
    red[t] = mx; __syncthreads();
    for (int oo = 128; oo; oo >>= 1) { if (t < oo) red[t] = fmaxf(red[t], red[t + oo]); __syncthreads(); }
    mx = red[0]; __syncthreads();
    float s = 0.f;
#pragma unroll
    for (int i = 0; i < 4; i++) {
        vals[i].x = __expf(vals[i].x - mx); vals[i].y = __expf(vals[i].y - mx);
        vals[i].z = __expf(vals[i].z - mx); vals[i].w = __expf(vals[i].w - mx);
        s += vals[i].x + vals[i].y + vals[i].z + vals[i].w;
    }
    red[t] = s; __syncthreads();
    for (int oo = 128; oo; oo >>= 1) { if (t < oo) red[t] += red[t + oo]; __syncthreads(); }
    const float inv = 1.f / red[0];
#pragma unroll
    for (int i = 0; i < 4; i++) {
        __half2 h0 = __floats2half2_rn(vals[i].x * inv, vals[i].y * inv);
        __half2 h1 = __floats2half2_rn(vals[i].z * inv, vals[i].w * inv);
        *reinterpret_cast<__half2*>(o + t * 16 + i * 4)     = h0;
        *reinterpret_cast<__half2*>(o + t * 16 + i * 4 + 2) = h1;
    }
}

// LayerNorm over fp32 rows of 512; optional fp32 residual; OT output.
template<typename OT>
__global__ __launch_bounds__(256)
void ln_k(const float* __restrict__ X, const float* __restrict__ g,
          const float* __restrict__ b, const float* __restrict__ res,
          OT* __restrict__ out)
{
    const long row = blockIdx.x;
    const float* p = X + row * 512;
    const int t = threadIdx.x;
    float v0 = p[t], v1 = p[t + 256];
    __shared__ float red[256];
    red[t] = v0 + v1; __syncthreads();
    for (int o = 128; o; o >>= 1) { if (t < o) red[t] += red[t + o]; __syncthreads(); }
    const float mu = red[0] * (1.f / 512.f);
    __syncthreads();
    const float d0 = v0 - mu, d1 = v1 - mu;
    red[t] = d0 * d0 + d1 * d1; __syncthreads();
    for (int o = 128; o; o >>= 1) { if (t < o) red[t] += red[t + o]; __syncthreads(); }
    const float rs = rsqrtf(red[0] * (1.f / 512.f) + 1e-5f);
    float o0 = d0 * rs * g[t]       + b[t];
    float o1 = d1 * rs * g[t + 256] + b[t + 256];
    if (res) { o0 += res[row * 512 + t]; o1 += res[row * 512 + t + 256]; }
    if constexpr (sizeof(OT) == 2) {
        out[row * 512 + t]       = __float2half_rn(o0);
        out[row * 512 + t + 256] = __float2half_rn(o1);
    } else {
        out[row * 512 + t]       = o0;
        out[row * 512 + t + 256] = o1;
    }
}

template <typename P, typename T>
static P sym(T& s) { void* p = nullptr; cudaGetSymbolAddress(&p, s); return (P)p; }

extern "C" void kernel_launch(void* const* d_in, const int* in_sizes, int n_in,
                              void* d_out, int out_size)
{
    const float* x   = (const float*)d_in[0];
    const float* src = (const float*)d_in[1];
    const float* Wq  = (const float*)d_in[2];
    const float* Wk  = (const float*)d_in[3];
    const float* Wv  = (const float*)d_in[4];
    const float* Wm  = (const float*)d_in[5];
    const float* W1  = (const float*)d_in[6];
    const float* W2  = (const float*)d_in[7];
    const float* g1  = (const float*)d_in[8];
    const float* b1  = (const float*)d_in[9];
    const float* g2  = (const float*)d_in[10];
    const float* b2  = (const float*)d_in[11];
    float* out = (float*)d_out;

    __half *xh = sym<__half*>(g_xh), *sh = sym<__half*>(g_sh);
    __half *q  = sym<__half*>(g_q),  *k  = sym<__half*>(g_k),  *vT = sym<__half*>(g_vT);
    __half *sc = sym<__half*>(g_sc), *ms = sym<__half*>(g_ms), *m1 = sym<__half*>(g_m1);
    __half *u  = sym<__half*>(g_u);
    float  *scf = sym<float*>(g_scf);
    float  *q2 = sym<float*>(g_q2),  *k2 = sym<float*>(g_k2);
    float  *mm = sym<float*>(g_mm),  *zz = sym<float*>(g_z);
    __half *wqT = sym<__half*>(g_WqT), *wkT = sym<__half*>(g_WkT), *wvT = sym<__half*>(g_WvT);
    __half *wmT = sym<__half*>(g_WmT), *w1T = sym<__half*>(g_W1T), *w2T = sym<__half*>(g_W2T);

    // 0a: input conversions fp32 -> fp16
    f2h_k<<<ML*DM/1024, 256>>>(x,   xh);
    f2h_k<<<MS*DM/1024, 256>>>(src, sh);

    // 0b: weight transposes -> fp16 (all GEMMs run NT with K-major B' = W^T)
    transpose_h<<<dim3(DM/32,   DM/32),   256>>>(Wq, wqT, DM,   DM);
    transpose_h<<<dim3(DM/32,   DM/32),   256>>>(Wk, wkT, DM,   DM);
    transpose_h<<<dim3(DM/32,   DM/32),   256>>>(Wv, wvT, DM,   DM);
    transpose_h<<<dim3(DM/32,   DM/32),   256>>>(Wm, wmT, DM,   DM);
    transpose_h<<<dim3(2*DM/32, 2*DM/32), 256>>>(W1, w1T, 2*DM, 2*DM);
    transpose_h<<<dim3(DM/32,   2*DM/32), 256>>>(W2, w2T, 2*DM, DM);

    // 1-2: q/k projections (flattened over batch)
    hgemm_k<0, __half><<<dim3(DM/128, ML/128, 1), 256>>>(xh, nullptr, wqT, q, DM, DM, DM, DM, 0, 0, 0, nullptr, nullptr, 0, 0);
    hgemm_k<0, __half><<<dim3(DM/128, MS/128, 1), 256>>>(sh, nullptr, wkT, k, DM, DM, DM, DM, 0, 0, 0, nullptr, nullptr, 0, 0);

    // 3: vT = (src @ Wv)^T computed directly: C[d][s] = sum_k WvT[d][k]*src[s][k]
    hgemm_k<0, __half><<<dim3(SK/128, DM/128, NB), 256>>>(wvT, nullptr, sh, vT,
        DM, DM, DM, SK, 0, (long)SK*DM, (long)DM*SK, nullptr, nullptr, 0, 0);

    // 4-5: squared row norms (fp32 accumulate over the same fp16 values the MMA sees)
    rownorm_h<<<ML / 8, 256>>>(q, q2);
    rownorm_h<<<MS / 8, 256>>>(k, k2);

    // 6: dist = sqrt(max(q2 + k2 - 2 q.k, 0))  (batched NT, fused epilogue, fp32 out)
    hgemm_k<1, float><<<dim3(SK/128, LQ/128, NB), 256>>>(q, nullptr, k, scf,
        DM, DM, DM, SK, (long)LQ*DM, (long)SK*DM, (long)LQ*SK, q2, k2, LQ, SK);

    // 7: softmax over S (fp32 in, fp16 out)
    softmax_fh<<<ML, 256>>>(scf, sc);

    // 8: message = attn @ v  (A = attn [LQ,SK], B' = vT [DM,SK])
    hgemm_k<0, __half><<<dim3(DM/128, LQ/128, NB), 256>>>(sc, nullptr, vT, ms,
        SK, SK, SK, DM, (long)LQ*SK, (long)DM*SK, (long)LQ*DM, nullptr, nullptr, 0, 0);

    // 9: mm = message @ Wm  (fp32 out -> layernorm)
    hgemm_k<0, float><<<dim3(DM/128, ML/128, 1), 256>>>(ms, nullptr, wmT, mm, DM, DM, DM, DM, 0, 0, 0, nullptr, nullptr, 0, 0);

    // 10: layernorm1 -> fp16
    ln_k<__half><<<ML, 256>>>(mm, g1, b1, nullptr, m1);

    // 11: u = relu([x | m1] @ W1)  (fused concat + relu, fp16 out)
    hgemm_k<2, __half><<<dim3(2*DM/128, ML/128, 1), 256>>>(xh, m1, w1T, u, 2*DM, DM, 2*DM, 2*DM, 0, 0, 0, nullptr, nullptr, 0, 0);

    // 12: z = u @ W2  (fp32 out -> layernorm)
    hgemm_k<0, float><<<dim3(DM/128, ML/128, 1), 256>>>(u, nullptr, w2T, zz, 2*DM, 2*DM, 2*DM, DM, 0, 0, 0, nullptr, nullptr, 0, 0);

    // 13: out = x + layernorm2(z)
    ln_k<float><<<ML, 256>>>(zz, g2, b2, x, out);
}

// round 11
// speedup vs baseline: 5.6548x; 1.0324x over previous
#include <cuda_runtime.h>
#include <cuda_fp16.h>
#include <math.h>
#include <stdint.h>

// Problem dims
#define NB 8
#define LQ 1024
#define SK 4096
#define DM 512
#define ML (NB*LQ)   // 8192
#define MS (NB*SK)   // 32768
#define BKH 32       // k-chunk (halves) per buffer = two k16 MMA steps
#define PADK 40      // padded row stride in halves (conflict-free LDS + LDSM)
#define NSTAGE 3
#define SMEM_BYTES (NSTAGE * 2 * 128 * PADK * 2)   // 61440

// ---------------------------------------------------------------------------
// Scratch (device globals: no allocations allowed)
// ---------------------------------------------------------------------------
__device__ __half g_xh [ML*DM];
__device__ __half g_sh [MS*DM];
__device__ __half g_q  [ML*DM];
__device__ __half g_k  [MS*DM];
__device__ __half g_vT [(size_t)NB*DM*SK];
__device__ float  g_q2 [ML];
__device__ float  g_k2 [MS];
__device__ float  g_scf[(size_t)NB*LQ*SK];   // fp32 distances
__device__ __half g_sc [(size_t)NB*LQ*SK];   // fp16 attn weights
__device__ __half g_ms [ML*DM];
__device__ float  g_mm [ML*DM];
__device__ __half g_m1 [ML*DM];
__device__ __half g_u  [ML*2*DM];
__device__ float  g_z  [ML*DM];
__device__ __half g_WqT[DM*DM];
__device__ __half g_WkT[DM*DM];
__device__ __half g_WvT[DM*DM];
__device__ __half g_WmT[DM*DM];
__device__ __half g_W1T[2*DM*2*DM];
__device__ __half g_W2T[DM*2*DM];

__device__ __forceinline__ uint32_t s2u(const void* p) {
    uint32_t a;
    asm("{ .reg .u64 t; cvta.to.shared.u64 t, %1; cvt.u32.u64 %0, t; }" : "=r"(a) : "l"(p));
    return a;
}

__device__ __forceinline__ void mma_f16(float c[4], const unsigned a[4], const unsigned b[2]) {
    asm("mma.sync.aligned.m16n8k16.row.col.f32.f16.f16.f32 "
        "{%0,%1,%2,%3}, {%4,%5,%6,%7}, {%8,%9}, {%0,%1,%2,%3};"
        : "+f"(c[0]), "+f"(c[1]), "+f"(c[2]), "+f"(c[3])
        : "r"(a[0]), "r"(a[1]), "r"(a[2]), "r"(a[3]), "r"(b[0]), "r"(b[1]));
}

__device__ __forceinline__ void ldsm4(unsigned r[4], uint32_t addr) {
    asm volatile("ldmatrix.sync.aligned.m8n8.x4.shared.b16 {%0,%1,%2,%3}, [%4];"
        : "=r"(r[0]), "=r"(r[1]), "=r"(r[2]), "=r"(r[3]) : "r"(addr));
}

__device__ __forceinline__ void cp16(uint32_t dst, const void* src) {
    asm volatile("cp.async.cg.shared.global [%0], [%1], 16;" :: "r"(dst), "l"(src));
}

// ---------------------------------------------------------------------------
// fp16 tensor-core GEMM (fp32 accumulate): C[M,N] = A[M,K] @ B'[N,K]^T  (NT)
// fp16 operands in gmem, 3-stage cp.async pipeline, ldmatrix fragment loads,
// 256 threads = 8 warps (4m x 2n), warp tile 32x64 via m16n8k16.
// MODE 0: plain   MODE 1: dist = sqrt(max(e0[m]+e1[n]-2*acc, 0))
// MODE 2: A = virtual concat [A | A1] along K (each half lda), relu epilogue
// OT = float or __half output.
// smem layout (dynamic): As[stage][128][PADK] then Bs[stage][128][PADK]
// ---------------------------------------------------------------------------
template<int MODE, typename OT>
__global__ __launch_bounds__(256)
void hgemm_k(const __half* __restrict__ A, const __half* __restrict__ A1,
             const __half* __restrict__ B, OT* __restrict__ C,
             int K, int lda, int ldb, int ldc,
             long sA, long sB, long sC,
             const float* __restrict__ e0, const float* __restrict__ e1,
             int se0, int se1)
{
    extern __shared__ __align__(16) __half smem[];
    __half* AsBase = smem;                         // NSTAGE * 128*PADK
    __half* BsBase = smem + NSTAGE * 128 * PADK;   // NSTAGE * 128*PADK

    const int z = blockIdx.z;
    A += (long)z * sA;
    if (MODE == 2) A1 += (long)z * sA;
    B += (long)z * sB;
    C += (long)z * sC;
    const float* E0 = (MODE == 1) ? (e0 + (long)z * se0) : nullptr;
    const float* E1 = (MODE == 1) ? (e1 + (long)z * se1) : nullptr;

    const int t  = threadIdx.x;
    const int m0 = blockIdx.y * 128;
    const int n0 = blockIdx.x * 128;

    const int warpId = t >> 5;
    const int lane   = t & 31;
    const int mb     = (warpId >> 1) * 32;   // 0,32,64,96
    const int nb     = (warpId & 1) * 64;    // 0,64
    const int gq     = lane >> 2;            // 0..7
    const int tg     = lane & 3;             // 0..3

    // ldmatrix per-lane source rows/cols
    const int lrowA = lane & 15;
    const int kcolA = (lane >> 4) * 8;
    const int lrowB = ((lane >> 4) << 3) + (lane & 7);
    const int kcolB = ((lane >> 3) & 1) * 8;

    // staging: tile = 128 rows x 32 halves; 512 16B-chunks/operand, 2 per thread
    const int r0s = t >> 2,          c0s = (t & 3) * 8;
    const int r1s = (t + 256) >> 2;

    float acc[2][8][4];
#pragma unroll
    for (int i = 0; i < 2; i++)
#pragma unroll
        for (int j = 0; j < 8; j++)
#pragma unroll
            for (int r = 0; r < 4; r++) acc[i][j][r] = 0.f;

    const int NKT = K / BKH;

    auto stage = [&](int kt, int b) {
        __half* As = AsBase + b * 128 * PADK;
        __half* Bs = BsBase + b * 128 * PADK;
        const int k0 = kt * BKH;
        const __half* Asrc = A; int kk0 = k0;
        if (MODE == 2 && k0 >= DM) { Asrc = A1; kk0 = k0 - DM; }
        cp16(s2u(As + r0s * PADK + c0s), Asrc + (long)(m0 + r0s) * lda + kk0 + c0s);
        cp16(s2u(As + r1s * PADK + c0s), Asrc + (long)(m0 + r1s) * lda + kk0 + c0s);
        cp16(s2u(Bs + r0s * PADK + c0s), B + (long)(n0 + r0s) * ldb + k0 + c0s);
        cp16(s2u(Bs + r1s * PADK + c0s), B + (long)(n0 + r1s) * ldb + k0 + c0s);
        asm volatile("cp.async.commit_group;");
    };

    stage(0, 0);
    stage(1, 1);

    int buf = 0;
    for (int kt = 0; kt < NKT; kt++) {
        asm volatile("cp.async.wait_group 1;");
        __syncthreads();
        if (kt + 2 < NKT) stage(kt + 2, (kt + 2) % NSTAGE);

        const uint32_t baseA = s2u(AsBase + buf * 128 * PADK);
        const uint32_t baseB = s2u(BsBase + buf * 128 * PADK);

#pragma unroll
        for (int ks = 0; ks < BKH; ks += 16) {
            unsigned a[2][4], b[8][2];
#pragma unroll
            for (int i = 0; i < 2; i++)
                ldsm4(a[i], baseA + (uint32_t)((mb + i * 16 + lrowA) * PADK + ks + kcolA) * 2u);
#pragma unroll
            for (int j2 = 0; j2 < 4; j2++) {
                unsigned r[4];
                ldsm4(r, baseB + (uint32_t)((nb + j2 * 16 + lrowB) * PADK + ks + kcolB) * 2u);
                b[2*j2    ][0] = r[0]; b[2*j2    ][1] = r[1];
                b[2*j2 + 1][0] = r[2]; b[2*j2 + 1][1] = r[3];
            }
#pragma unroll
            for (int i = 0; i < 2; i++)
#pragma unroll
                for (int j = 0; j < 8; j++)
                    mma_f16(acc[i][j], a[i], b[j]);
        }
        buf = (buf + 1) % NSTAGE;
        __syncthreads();
    }

    // ---- epilogue (fragment: c0,c1 = row gq, cols 2tg..+1; c2,c3 = row gq+8)
#pragma unroll
    for (int i = 0; i < 2; i++) {
        const int row0 = m0 + mb + i * 16 + gq;
        const int row1 = row0 + 8;
#pragma unroll
        for (int j = 0; j < 8; j++) {
            const int col0 = n0 + nb + j * 8 + tg * 2;
            float v00 = acc[i][j][0], v01 = acc[i][j][1];
            float v10 = acc[i][j][2], v11 = acc[i][j][3];
            if (MODE == 1) {
                const float e00 = E0[row0], e01 = E0[row1];
                const float f0 = E1[col0], f1 = E1[col0 + 1];
                v00 = sqrtf(fmaxf(e00 + f0 - 2.f * v00, 0.f));
                v01 = sqrtf(fmaxf(e00 + f1 - 2.f * v01, 0.f));
                v10 = sqrtf(fmaxf(e01 + f0 - 2.f * v10, 0.f));
                v11 = sqrtf(fmaxf(e01 + f1 - 2.f * v11, 0.f));
            }
            if (MODE == 2) {
                v00 = fmaxf(v00, 0.f); v01 = fmaxf(v01, 0.f);
                v10 = fmaxf(v10, 0.f); v11 = fmaxf(v11, 0.f);
            }
            if constexpr (sizeof(OT) == 2) {
                *reinterpret_cast<__half2*>((__half*)C + (long)row0 * ldc + col0) = __floats2half2_rn(v00, v01);
                *reinterpret_cast<__half2*>((__half*)C + (long)row1 * ldc + col0) = __floats2half2_rn(v10, v11);
            } else {
                *reinterpret_cast<float2*>((float*)C + (long)row0 * ldc + col0) = make_float2(v00, v01);
                *reinterpret_cast<float2*>((float*)C + (long)row1 * ldc + col0) = make_float2(v10, v11);
            }
        }
    }
}

// ---------------------------------------------------------------------------
// Fused prep: fp32->fp16 conversion of x and source, plus all 6 weight
// transposes (fp32 [R,C] -> fp16 [C,R]), dispatched by blockIdx.x range.
// ---------------------------------------------------------------------------
#define XBLK (ML*DM/1024)          // 4096
#define SBLK (MS*DM/1024)          // 16384
#define TQ   256                   // 512x512 -> (512/32)*(512/32)
#define TW1  1024                  // 1024x1024
#define TW2  512                   // W2 [1024,512]: (512/32)*(1024/32)

__global__ __launch_bounds__(256)
void prep_k(const float* __restrict__ x, const float* __restrict__ src,
            __half* __restrict__ xh, __half* __restrict__ sh,
            const float* __restrict__ Wq, const float* __restrict__ Wk,
            const float* __restrict__ Wv, const float* __restrict__ Wm,
            const float* __restrict__ W1, const float* __restrict__ W2,
            __half* __restrict__ wqT, __half* __restrict__ wkT,
            __half* __restrict__ wvT, __half* __restrict__ wmT,
            __half* __restrict__ w1T, __half* __restrict__ w2T)
{
    int b = blockIdx.x;
    if (b < XBLK + SBLK) {
        const float* in = (b < XBLK) ? x : src;
        __half* outp    = (b < XBLK) ? xh : sh;
        const long base = (b < XBLK) ? (long)b * 1024 : (long)(b - XBLK) * 1024;
        const long i = base + threadIdx.x * 4;
        float4 v = *reinterpret_cast<const float4*>(in + i);
        *reinterpret_cast<__half2*>(outp + i)     = __floats2half2_rn(v.x, v.y);
        *reinterpret_cast<__half2*>(outp + i + 2) = __floats2half2_rn(v.z, v.w);
        return;
    }
    b -= XBLK + SBLK;
    const float* in; __half* outp; int R, C, tile;
    if      (b < TQ)                    { in = Wq; outp = wqT; R = DM;   C = DM;   tile = b; }
    else if (b < 2*TQ)                  { in = Wk; outp = wkT; R = DM;   C = DM;   tile = b - TQ; }
    else if (b < 3*TQ)                  { in = Wv; outp = wvT; R = DM;   C = DM;   tile = b - 2*TQ; }
    else if (b < 4*TQ)                  { in = Wm; outp = wmT; R = DM;   C = DM;   tile = b - 3*TQ; }
    else if (b < 4*TQ + TW1)            { in = W1; outp = w1T; R = 2*DM; C = 2*DM; tile = b - 4*TQ; }
    else                                { in = W2; outp = w2T; R = 2*DM; C = DM;   tile = b - 4*TQ - TW1; }
    const int ntx = C / 32;
    const int c0 = (tile % ntx) * 32, r0 = (tile / ntx) * 32;
    __shared__ float tf[32][33];
    const int tx = threadIdx.x & 31, ty = threadIdx.x >> 5;
#pragma unroll
    for (int i = 0; i < 32; i += 8)
        tf[ty + i][tx] = in[(long)(r0 + ty + i) * C + c0 + tx];
    __syncthreads();
#pragma unroll
    for (int i = 0; i < 32; i += 8)
        outp[(long)(c0 + ty + i) * R + r0 + tx] = __float2half_rn(tf[tx][ty + i]);
}

// Row squared-norms over fp16 rows of 512 for q then k, fp32 accumulate.
__global__ __launch_bounds__(256)
void rownorm2_k(const __half* __restrict__ Q, const __half* __restrict__ Kk,
                float* __restrict__ oq, float* __restrict__ ok)
{
    int row  = blockIdx.x * 8 + (threadIdx.x >> 5);
    const int lane = threadIdx.x & 31;
    const __half* X; float* o;
    if (row < ML) { X = Q; o = oq; }
    else          { X = Kk; o = ok; row -= ML; }
    const __half2* p = reinterpret_cast<const __half2*>(X + (long)row * DM);
    float s = 0.f;
#pragma unroll
    for (int c = 0; c < 8; c++) {
        float2 v = __half22float2(p[lane + c * 32]);
        s = fmaf(v.x, v.x, fmaf(v.y, v.y, s));
    }
#pragma unroll
    for (int o2 = 16; o2; o2 >>= 1) s += __shfl_xor_sync(0xffffffffu, s, o2);
    if (lane == 0) o[row] = s;
}

// Softmax over rows of 4096: read fp32 dist, write fp16 attn. One block/row.
__global__ __launch_bounds__(256)
void softmax_fh(const float* __restrict__ scf, __half* __restrict__ sc)
{
    const float* p = scf + (long)blockIdx.x * 4096;
    __half* o = sc + (long)blockIdx.x * 4096;
    const int t = threadIdx.x;
    float4 vals[4];
    float mx = -1e30f;
#pragma unroll
    for (int i = 0; i < 4; i++) {
        vals[i] = *reinterpret_cast<const float4*>(p + t * 16 + i * 4);
        mx = fmaxf(mx, fmaxf(fmaxf(vals[i].x, vals[i].y), fmaxf(vals[i].z, vals[i].w)));
    }
    __shared__ float red[256];
    red[t] = mx; __syncthreads();
    for (int oo = 128; oo; oo >>= 1) { if (t < oo) red[t] = fmaxf(red[t], red[t + oo]); __syncthreads(); }
    mx = red[0]; __syncthreads();
    float s = 0.f;
#pragma unroll
    for (int i = 0; i < 4; i++) {
        vals[i].x = __expf(vals[i].x - mx); vals[i].y = __expf(vals[i].y - mx);
        vals[i].z = __expf(vals[i].z - mx); vals[i].w = __expf(vals[i].w - mx);
        s += vals[i].x + vals[i].y + vals[i].z + vals[i].w;
    }
    red[t] = s; __syncthreads();
    for (int oo = 128; oo; oo >>= 1) { if (t < oo) red[t] += red[t + oo]; __syncthreads(); }
    const float inv = 1.f / red[0];
#pragma unroll
    for (int i = 0; i < 4; i++) {
        __half2 h0 = __floats2half2_rn(vals[i].x * inv, vals[i].y * inv);
        __half2 h1 = __floats2half2_rn(vals[i].z * inv, vals[i].w * inv);
        *reinterpret_cast<__half2*>(o + t * 16 + i * 4)     = h0;
        *reinterpret_cast<__half2*>(o + t * 16 + i * 4 + 2) = h1;
    }
}

// LayerNorm over fp32 rows of 512; optional fp32 residual; OT output.
template<typename OT>
__global__ __launch_bounds__(256)
void ln_k(const float* __restrict__ X, const float* __restrict__ g,
          const float* __restrict__ b, const float* __restrict__ res,
          OT* __restrict__ out)
{
    const long row = blockIdx.x;
    const float* p = X + row * 512;
    const int t = threadIdx.x;
    float v0 = p[t], v1 = p[t + 256];
    __shared__ float red[256];
    red[t] = v0 + v1; __syncthreads();
    for (int o = 128; o; o >>= 1) { if (t < o) red[t] += red[t + o]; __syncthreads(); }
    const float mu = red[0] * (1.f / 512.f);
    __syncthreads();
    const float d0 = v0 - mu, d1 = v1 - mu;
    red[t] = d0 * d0 + d1 * d1; __syncthreads();
    for (int o = 128; o; o >>= 1) { if (t < o) red[t] += red[t + o]; __syncthreads(); }
    const float rs = rsqrtf(red[0] * (1.f / 512.f) + 1e-5f);
    float o0 = d0 * rs * g[t]       + b[t];
    float o1 = d1 * rs * g[t + 256] + b[t + 256];
    if (res) { o0 += res[row * 512 + t]; o1 += res[row * 512 + t + 256]; }
    if constexpr (sizeof(OT) == 2) {
        out[row * 512 + t]       = __float2half_rn(o0);
        out[row * 512 + t + 256] = __float2half_rn(o1);
    } else {
        out[row * 512 + t]       = o0;
        out[row * 512 + t + 256] = o1;
    }
}

template <typename P, typename T>
static P sym(T& s) { void* p = nullptr; cudaGetSymbolAddress(&p, s); return (P)p; }

extern "C" void kernel_launch(void* const* d_in, const int* in_sizes, int n_in,
                              void* d_out, int out_size)
{
    const float* x   = (const float*)d_in[0];
    const float* src = (const float*)d_in[1];
    const float* Wq  = (const float*)d_in[2];
    const float* Wk  = (const float*)d_in[3];
    const float* Wv  = (const float*)d_in[4];
    const float* Wm  = (const float*)d_in[5];
    const float* W1  = (const float*)d_in[6];
    const float* W2  = (const float*)d_in[7];
    const float* g1  = (const float*)d_in[8];
    const float* b1  = (const float*)d_in[9];
    const float* g2  = (const float*)d_in[10];
    const float* b2  = (const float*)d_in[11];
    float* out = (float*)d_out;

    __half *xh = sym<__half*>(g_xh), *sh = sym<__half*>(g_sh);
    __half *q  = sym<__half*>(g_q),  *k  = sym<__half*>(g_k),  *vT = sym<__half*>(g_vT);
    __half *sc = sym<__half*>(g_sc), *ms = sym<__half*>(g_ms), *m1 = sym<__half*>(g_m1);
    __half *u  = sym<__half*>(g_u);
    float  *scf = sym<float*>(g_scf);
    float  *q2 = sym<float*>(g_q2),  *k2 = sym<float*>(g_k2);
    float  *mm = sym<float*>(g_mm),  *zz = sym<float*>(g_z);
    __half *wqT = sym<__half*>(g_WqT), *wkT = sym<__half*>(g_WkT), *wvT = sym<__half*>(g_WvT);
    __half *wmT = sym<__half*>(g_WmT), *w1T = sym<__half*>(g_W1T), *w2T = sym<__half*>(g_W2T);

    // opt-in to 60KB dynamic smem (idempotent)
    cudaFuncSetAttribute(hgemm_k<0, __half>, cudaFuncAttributeMaxDynamicSharedMemorySize, SMEM_BYTES);
    cudaFuncSetAttribute(hgemm_k<0, float>,  cudaFuncAttributeMaxDynamicSharedMemorySize, SMEM_BYTES);
    cudaFuncSetAttribute(hgemm_k<1, float>,  cudaFuncAttributeMaxDynamicSharedMemorySize, SMEM_BYTES);
    cudaFuncSetAttribute(hgemm_k<2, __half>, cudaFuncAttributeMaxDynamicSharedMemorySize, SMEM_BYTES);

    // 0: fused prep (x/src -> fp16, all weight transposes -> fp16 K-major)
    prep_k<<<XBLK + SBLK + 4*TQ + TW1 + TW2, 256>>>(x, src, xh, sh,
        Wq, Wk, Wv, Wm, W1, W2, wqT, wkT, wvT, wmT, w1T, w2T);

    // 1-2: q/k projections (flattened over batch)
    hgemm_k<0, __half><<<dim3(DM/128, ML/128, 1), 256, SMEM_BYTES>>>(xh, nullptr, wqT, q, DM, DM, DM, DM, 0, 0, 0, nullptr, nullptr, 0, 0);
    hgemm_k<0, __half><<<dim3(DM/128, MS/128, 1), 256, SMEM_BYTES>>>(sh, nullptr, wkT, k, DM, DM, DM, DM, 0, 0, 0, nullptr, nullptr, 0, 0);

    // 3: vT = (src @ Wv)^T computed directly: C[d][s] = sum_k WvT[d][k]*src[s][k]
    hgemm_k<0, __half><<<dim3(SK/128, DM/128, NB), 256, SMEM_BYTES>>>(wvT, nullptr, sh, vT,
        DM, DM, DM, SK, 0, (long)SK*DM, (long)DM*SK, nullptr, nullptr, 0, 0);

    // 4: squared row norms for q and k (one launch)
    rownorm2_k<<<(ML + MS) / 8, 256>>>(q, k, q2, k2);

    // 5: dist = sqrt(max(q2 + k2 - 2 q.k, 0))  (batched NT, fused epilogue, fp32 out)
    hgemm_k<1, float><<<dim3(SK/128, LQ/128, NB), 256, SMEM_BYTES>>>(q, nullptr, k, scf,
        DM, DM, DM, SK, (long)LQ*DM, (long)SK*DM, (long)LQ*SK, q2, k2, LQ, SK);

    // 6: softmax over S (fp32 in, fp16 out)
    softmax_fh<<<ML, 256>>>(scf, sc);

    // 7: message = attn @ v  (A = attn [LQ,SK], B' = vT [DM,SK])
    hgemm_k<0, __half><<<dim3(DM/128, LQ/128, NB), 256, SMEM_BYTES>>>(sc, nullptr, vT, ms,
        SK, SK, SK, DM, (long)LQ*SK, (long)DM*SK, (long)LQ*DM, nullptr, nullptr, 0, 0);

    // 8: mm = message @ Wm  (fp32 out -> layernorm)
    hgemm_k<0, float><<<dim3(DM/128, ML/128, 1), 256, SMEM_BYTES>>>(ms, nullptr, wmT, mm, DM, DM, DM, DM, 0, 0, 0, nullptr, nullptr, 0, 0);

    // 9: layernorm1 -> fp16
    ln_k<__half><<<ML, 256>>>(mm, g1, b1, nullptr, m1);

    // 10: u = relu([x | m1] @ W1)  (fused concat + relu, fp16 out)
    hgemm_k<2, __half><<<dim3(2*DM/128, ML/128, 1), 256, SMEM_BYTES>>>(xh, m1, w1T, u, 2*DM, DM, 2*DM, 2*DM, 0, 0, 0, nullptr, nullptr, 0, 0);

    // 11: z = u @ W2  (fp32 out -> layernorm)
    hgemm_k<0, float><<<dim3(DM/128, ML/128, 1), 256, SMEM_BYTES>>>(u, nullptr, w2T, zz, 2*DM, 2*DM, 2*DM, DM, 0, 0, 0, nullptr, nullptr, 0, 0);

    // 12: out = x + layernorm2(z)
    ln_k<float><<<ML, 256>>>(zz, g2, b2, x, out);
}

// round 12
// speedup vs baseline: 6.3830x; 1.1288x over previous
#include <cuda_runtime.h>
#include <cuda_fp16.h>
#include <math.h>
#include <stdint.h>

// Problem dims
#define NB 8
#define LQ 1024
#define SK 4096
#define DM 512
#define ML (NB*LQ)   // 8192
#define MS (NB*SK)   // 32768
#define BKH 64       // k-chunk (halves) per stage = four k16 MMA steps
#define PADK 72      // padded row stride in halves (conflict-free LDS + LDSM)
#define NSTAGE 3
#define SMEM_BYTES (NSTAGE * 2 * 128 * PADK * 2)   // 110592

// ---------------------------------------------------------------------------
// Scratch (device globals: no allocations allowed)
// ---------------------------------------------------------------------------
__device__ __half g_xh [ML*DM];
__device__ __half g_sh [MS*DM];
__device__ __half g_q  [ML*DM];
__device__ __half g_k  [MS*DM];
__device__ __half g_vT [(size_t)NB*DM*SK];
__device__ float  g_q2 [ML];
__device__ float  g_k2 [MS];
__device__ float  g_scf[(size_t)NB*LQ*SK];   // fp32 distances
__device__ __half g_sc [(size_t)NB*LQ*SK];   // fp16 attn weights
__device__ __half g_ms [ML*DM];
__device__ float  g_mm [ML*DM];
__device__ __half g_m1 [ML*DM];
__device__ __half g_u  [ML*2*DM];
__device__ float  g_z  [ML*DM];
__device__ __half g_WqT[DM*DM];
__device__ __half g_WkT[DM*DM];
__device__ __half g_WvT[DM*DM];
__device__ __half g_WmT[DM*DM];
__device__ __half g_W1T[2*DM*2*DM];
__device__ __half g_W2T[DM*2*DM];

__device__ __forceinline__ uint32_t s2u(const void* p) {
    uint32_t a;
    asm("{ .reg .u64 t; cvta.to.shared.u64 t, %1; cvt.u32.u64 %0, t; }" : "=r"(a) : "l"(p));
    return a;
}

__device__ __forceinline__ void mma_f16(float c[4], const unsigned a[4], const unsigned b[2]) {
    asm("mma.sync.aligned.m16n8k16.row.col.f32.f16.f16.f32 "
        "{%0,%1,%2,%3}, {%4,%5,%6,%7}, {%8,%9}, {%0,%1,%2,%3};"
        : "+f"(c[0]), "+f"(c[1]), "+f"(c[2]), "+f"(c[3])
        : "r"(a[0]), "r"(a[1]), "r"(a[2]), "r"(a[3]), "r"(b[0]), "r"(b[1]));
}

__device__ __forceinline__ void ldsm4(unsigned r[4], uint32_t addr) {
    asm volatile("ldmatrix.sync.aligned.m8n8.x4.shared.b16 {%0,%1,%2,%3}, [%4];"
        : "=r"(r[0]), "=r"(r[1]), "=r"(r[2]), "=r"(r[3]) : "r"(addr));
}

__device__ __forceinline__ void cp16(uint32_t dst, const void* src) {
    asm volatile("cp.async.cg.shared.global [%0], [%1], 16;" :: "r"(dst), "l"(src));
}

// ---------------------------------------------------------------------------
// fp16 tensor-core GEMM (fp32 accumulate): C[M,N] = A[M,K] @ B'[N,K]^T  (NT)
// fp16 operands in gmem, 3-stage cp.async pipeline with BK=64 halves/stage
// (one __syncthreads per stage), ldmatrix fragment loads, 256 threads = 8
// warps (4m x 2n), warp tile 32x64 via m16n8k16, 2 CTAs/SM.
// MODE 0: plain   MODE 1: dist = sqrt(max(e0[m]+e1[n]-2*acc, 0))
// MODE 2: A = virtual concat [A | A1] along K (each half lda), relu epilogue
// OT = float or __half output.
// smem layout (dynamic): As[stage][128][PADK] then Bs[stage][128][PADK]
// ---------------------------------------------------------------------------
template<int MODE, typename OT>
__global__ __launch_bounds__(256, 2)
void hgemm_k(const __half* __restrict__ A, const __half* __restrict__ A1,
             const __half* __restrict__ B, OT* __restrict__ C,
             int K, int lda, int ldb, int ldc,
             long sA, long sB, long sC,
             const float* __restrict__ e0, const float* __restrict__ e1,
             int se0, int se1)
{
    extern __shared__ __align__(16) __half smem[];
    __half* AsBase = smem;                         // NSTAGE * 128*PADK
    __half* BsBase = smem + NSTAGE * 128 * PADK;   // NSTAGE * 128*PADK

    const int z = blockIdx.z;
    A += (long)z * sA;
    if (MODE == 2) A1 += (long)z * sA;
    B += (long)z * sB;
    C += (long)z * sC;
    const float* E0 = (MODE == 1) ? (e0 + (long)z * se0) : nullptr;
    const float* E1 = (MODE == 1) ? (e1 + (long)z * se1) : nullptr;

    const int t  = threadIdx.x;
    const int m0 = blockIdx.y * 128;
    const int n0 = blockIdx.x * 128;

    const int warpId = t >> 5;
    const int lane   = t & 31;
    const int mb     = (warpId >> 1) * 32;   // 0,32,64,96
    const int nb     = (warpId & 1) * 64;    // 0,64
    const int gq     = lane >> 2;            // 0..7
    const int tg     = lane & 3;             // 0..3

    // ldmatrix per-lane source rows/cols
    const int lrowA = lane & 15;
    const int kcolA = (lane >> 4) * 8;
    const int lrowB = ((lane >> 4) << 3) + (lane & 7);
    const int kcolB = ((lane >> 3) & 1) * 8;

    // staging: tile = 128 rows x 64 halves = 1024 16B-chunks/operand, 4/thread
    //   chunk c = t + i*256: row = c>>3 (= (t>>3) + i*32), col8 = (c&7)*8
    const int rs = t >> 3;
    const int c8 = (t & 7) * 8;

    float acc[2][8][4];
#pragma unroll
    for (int i = 0; i < 2; i++)
#pragma unroll
        for (int j = 0; j < 8; j++)
#pragma unroll
            for (int r = 0; r < 4; r++) acc[i][j][r] = 0.f;

    const int NKT = K / BKH;

    auto stage = [&](int kt, int b) {
        __half* As = AsBase + b * 128 * PADK;
        __half* Bs = BsBase + b * 128 * PADK;
        const int k0 = kt * BKH;
        const __half* Asrc = A; int kk0 = k0;
        if (MODE == 2 && k0 >= DM) { Asrc = A1; kk0 = k0 - DM; }
#pragma unroll
        for (int i = 0; i < 4; i++) {
            const int row = rs + i * 32;
            cp16(s2u(As + row * PADK + c8), Asrc + (long)(m0 + row) * lda + kk0 + c8);
        }
#pragma unroll
        for (int i = 0; i < 4; i++) {
            const int row = rs + i * 32;
            cp16(s2u(Bs + row * PADK + c8), B + (long)(n0 + row) * ldb + k0 + c8);
        }
        asm volatile("cp.async.commit_group;");
    };

    stage(0, 0);
    stage(1, 1);

    for (int kt = 0; kt < NKT; kt++) {
        const int buf = kt % NSTAGE;
        asm volatile("cp.async.wait_group 1;");
        __syncthreads();
        if (kt + 2 < NKT) stage(kt + 2, (kt + 2) % NSTAGE);

        const uint32_t baseA = s2u(AsBase + buf * 128 * PADK);
        const uint32_t baseB = s2u(BsBase + buf * 128 * PADK);

#pragma unroll
        for (int ks = 0; ks < BKH; ks += 16) {
            unsigned a[2][4], b[8][2];
#pragma unroll
            for (int i = 0; i < 2; i++)
                ldsm4(a[i], baseA + (uint32_t)((mb + i * 16 + lrowA) * PADK + ks + kcolA) * 2u);
#pragma unroll
            for (int j2 = 0; j2 < 4; j2++) {
                unsigned r[4];
                ldsm4(r, baseB + (uint32_t)((nb + j2 * 16 + lrowB) * PADK + ks + kcolB) * 2u);
                b[2*j2    ][0] = r[0]; b[2*j2    ][1] = r[1];
                b[2*j2 + 1][0] = r[2]; b[2*j2 + 1][1] = r[3];
            }
#pragma unroll
            for (int i = 0; i < 2; i++)
#pragma unroll
                for (int j = 0; j < 8; j++)
                    mma_f16(acc[i][j], a[i], b[j]);
        }
    }

    // ---- epilogue (fragment: c0,c1 = row gq, cols 2tg..+1; c2,c3 = row gq+8)
#pragma unroll
    for (int i = 0; i < 2; i++) {
        const int row0 = m0 + mb + i * 16 + gq;
        const int row1 = row0 + 8;
#pragma unroll
        for (int j = 0; j < 8; j++) {
            const int col0 = n0 + nb + j * 8 + tg * 2;
            float v00 = acc[i][j][0], v01 = acc[i][j][1];
            float v10 = acc[i][j][2], v11 = acc[i][j][3];
            if (MODE == 1) {
                const float e00 = E0[row0], e01 = E0[row1];
                const float f0 = E1[col0], f1 = E1[col0 + 1];
                v00 = sqrtf(fmaxf(e00 + f0 - 2.f * v00, 0.f));
                v01 = sqrtf(fmaxf(e00 + f1 - 2.f * v01, 0.f));
                v10 = sqrtf(fmaxf(e01 + f0 - 2.f * v10, 0.f));
                v11 = sqrtf(fmaxf(e01 + f1 - 2.f * v11, 0.f));
            }
            if (MODE == 2) {
                v00 = fmaxf(v00, 0.f); v01 = fmaxf(v01, 0.f);
                v10 = fmaxf(v10, 0.f); v11 = fmaxf(v11, 0.f);
            }
            if constexpr (sizeof(OT) == 2) {
                *reinterpret_cast<__half2*>((__half*)C + (long)row0 * ldc + col0) = __floats2half2_rn(v00, v01);
                *reinterpret_cast<__half2*>((__half*)C + (long)row1 * ldc + col0) = __floats2half2_rn(v10, v11);
            } else {
                *reinterpret_cast<float2*>((float*)C + (long)row0 * ldc + col0) = make_float2(v00, v01);
                *reinterpret_cast<float2*>((float*)C + (long)row1 * ldc + col0) = make_float2(v10, v11);
            }
        }
    }
}

// ---------------------------------------------------------------------------
// Fused prep: fp32->fp16 conversion of x and source, plus all 6 weight
// transposes (fp32 [R,C] -> fp16 [C,R]), dispatched by blockIdx.x range.
// ---------------------------------------------------------------------------
#define XBLK (ML*DM/1024)          // 4096
#define SBLK (MS*DM/1024)          // 16384
#define TQ   256                   // 512x512 -> (512/32)*(512/32)
#define TW1  1024                  // 1024x1024
#define TW2  512                   // W2 [1024,512]: (512/32)*(1024/32)

__global__ __launch_bounds__(256)
void prep_k(const float* __restrict__ x, const float* __restrict__ src,
            __half* __restrict__ xh, __half* __restrict__ sh,
            const float* __restrict__ Wq, const float* __restrict__ Wk,
            const float* __restrict__ Wv, const float* __restrict__ Wm,
            const float* __restrict__ W1, const float* __restrict__ W2,
            __half* __restrict__ wqT, __half* __restrict__ wkT,
            __half* __restrict__ wvT, __half* __restrict__ wmT,
            __half* __restrict__ w1T, __half* __restrict__ w2T)
{
    int b = blockIdx.x;
    if (b < XBLK + SBLK) {
        const float* in = (b < XBLK) ? x : src;
        __half* outp    = (b < XBLK) ? xh : sh;
        const long base = (b < XBLK) ? (long)b * 1024 : (long)(b - XBLK) * 1024;
        const long i = base + threadIdx.x * 4;
        float4 v = *reinterpret_cast<const float4*>(in + i);
        *reinterpret_cast<__half2*>(outp + i)     = __floats2half2_rn(v.x, v.y);
        *reinterpret_cast<__half2*>(outp + i + 2) = __floats2half2_rn(v.z, v.w);
        return;
    }
    b -= XBLK + SBLK;
    const float* in; __half* outp; int R, C, tile;
    if      (b < TQ)                    { in = Wq; outp = wqT; R = DM;   C = DM;   tile = b; }
    else if (b < 2*TQ)                  { in = Wk; outp = wkT; R = DM;   C = DM;   tile = b - TQ; }
    else if (b < 3*TQ)                  { in = Wv; outp = wvT; R = DM;   C = DM;   tile = b - 2*TQ; }
    else if (b < 4*TQ)                  { in = Wm; outp = wmT; R = DM;   C = DM;   tile = b - 3*TQ; }
    else if (b < 4*TQ + TW1)            { in = W1; outp = w1T; R = 2*DM; C = 2*DM; tile = b - 4*TQ; }
    else                                { in = W2; outp = w2T; R = 2*DM; C = DM;   tile = b - 4*TQ - TW1; }
    const int ntx = C / 32;
    const int c0 = (tile % ntx) * 32, r0 = (tile / ntx) * 32;
    __shared__ float tf[32][33];
    const int tx = threadIdx.x & 31, ty = threadIdx.x >> 5;
#pragma unroll
    for (int i = 0; i < 32; i += 8)
        tf[ty + i][tx] = in[(long)(r0 + ty + i) * C + c0 + tx];
    __syncthreads();
#pragma unroll
    for (int i = 0; i < 32; i += 8)
        outp[(long)(c0 + ty + i) * R + r0 + tx] = __float2half_rn(tf[tx][ty + i]);
}

// Row squared-norms over fp16 rows of 512 for q then k, fp32 accumulate.
__global__ __launch_bounds__(256)
void rownorm2_k(const __half* __restrict__ Q, const __half* __restrict__ Kk,
                float* __restrict__ oq, float* __restrict__ ok)
{
    int row  = blockIdx.x * 8 + (threadIdx.x >> 5);
    const int lane = threadIdx.x & 31;
    const __half* X; float* o;
    if (row < ML) { X = Q; o = oq; }
    else          { X = Kk; o = ok; row -= ML; }
    const __half2* p = reinterpret_cast<const __half2*>(X + (long)row * DM);
    float s = 0.f;
#pragma unroll
    for (int c = 0; c < 8; c++) {
        float2 v = __half22float2(p[lane + c * 32]);
        s = fmaf(v.x, v.x, fmaf(v.y, v.y, s));
    }
#pragma unroll
    for (int o2 = 16; o2; o2 >>= 1) s += __shfl_xor_sync(0xffffffffu, s, o2);
    if (lane == 0) o[row] = s;
}

// Softmax over rows of 4096: read fp32 dist, write fp16 attn. One block/row.
__global__ __launch_bounds__(256)
void softmax_fh(const float* __restrict__ scf, __half* __restrict__ sc)
{
    const float* p = scf + (long)blockIdx.x * 4096;
    __half* o = sc + (long)blockIdx.x * 4096;
    const int t = threadIdx.x;
    float4 vals[4];
    float mx = -1e30f;
#pragma unroll
    for (int i = 0; i < 4; i++) {
        vals[i] = *reinterpret_cast<const float4*>(p + t * 16 + i * 4);
        mx = fmaxf(mx, fmaxf(fmaxf(vals[i].x, vals[i].y), fmaxf(vals[i].z, vals[i].w)));
    }
    __shared__ float red[256];
    red[t] = mx; __syncthreads();
    for (int oo = 128; oo; oo >>= 1) { if (t < oo) red[t] = fmaxf(red[t], red[t + oo]); __syncthreads(); }
    mx = red[0]; __syncthreads();
    float s = 0.f;
#pragma unroll
    for (int i = 0; i < 4; i++) {
        vals[i].x = __expf(vals[i].x - mx); vals[i].y = __expf(vals[i].y - mx);
        vals[i].z = __expf(vals[i].z - mx); vals[i].w = __expf(vals[i].w - mx);
        s += vals[i].x + vals[i].y + vals[i].z + vals[i].w;
    }
    red[t] = s; __syncthreads();
    for (int oo = 128; oo; oo >>= 1) { if (t < oo) red[t] += red[t + oo]; __syncthreads(); }
    const float inv = 1.f / red[0];
#pragma unroll
    for (int i = 0; i < 4; i++) {
        __half2 h0 = __floats2half2_rn(vals[i].x * inv, vals[i].y * inv);
        __half2 h1 = __floats2half2_rn(vals[i].z * inv, vals[i].w * inv);
        *reinterpret_cast<__half2*>(o + t * 16 + i * 4)     = h0;
        *reinterpret_cast<__half2*>(o + t * 16 + i * 4 + 2) = h1;
    }
}

// LayerNorm over fp32 rows of 512; optional fp32 residual; OT output.
template<typename OT>
__global__ __launch_bounds__(256)
void ln_k(const float* __restrict__ X, const float* __restrict__ g,
          const float* __restrict__ b, const float* __restrict__ res,
          OT* __restrict__ out)
{
    const long row = blockIdx.x;
    const float* p = X + row * 512;
    const int t = threadIdx.x;
    float v0 = p[t], v1 = p[t + 256];
    __shared__ float red[256];
    red[t] = v0 + v1; __syncthreads();
    for (int o = 128; o; o >>= 1) { if (t < o) red[t] += red[t + o]; __syncthreads(); }
    const float mu = red[0] * (1.f / 512.f);
    __syncthreads();
    const float d0 = v0 - mu, d1 = v1 - mu;
    red[t] = d0 * d0 + d1 * d1; __syncthreads();
    for (int o = 128; o; o >>= 1) { if (t < o) red[t] += red[t + o]; __syncthreads(); }
    const float rs = rsqrtf(red[0] * (1.f / 512.f) + 1e-5f);
    float o0 = d0 * rs * g[t]       + b[t];
    float o1 = d1 * rs * g[t + 256] + b[t + 256];
    if (res) { o0 += res[row * 512 + t]; o1 += res[row * 512 + t + 256]; }
    if constexpr (sizeof(OT) == 2) {
        out[row * 512 + t]       = __float2half_rn(o0);
        out[row * 512 + t + 256] = __float2half_rn(o1);
    } else {
        out[row * 512 + t]       = o0;
        out[row * 512 + t + 256] = o1;
    }
}

template <typename P, typename T>
static P sym(T& s) { void* p = nullptr; cudaGetSymbolAddress(&p, s); return (P)p; }

extern "C" void kernel_launch(void* const* d_in, const int* in_sizes, int n_in,
                              void* d_out, int out_size)
{
    const float* x   = (const float*)d_in[0];
    const float* src = (const float*)d_in[1];
    const float* Wq  = (const float*)d_in[2];
    const float* Wk  = (const float*)d_in[3];
    const float* Wv  = (const float*)d_in[4];
    const float* Wm  = (const float*)d_in[5];
    const float* W1  = (const float*)d_in[6];
    const float* W2  = (const float*)d_in[7];
    const float* g1  = (const float*)d_in[8];
    const float* b1  = (const float*)d_in[9];
    const float* g2  = (const float*)d_in[10];
    const float* b2  = (const float*)d_in[11];
    float* out = (float*)d_out;

    __half *xh = sym<__half*>(g_xh), *sh = sym<__half*>(g_sh);
    __half *q  = sym<__half*>(g_q),  *k  = sym<__half*>(g_k),  *vT = sym<__half*>(g_vT);
    __half *sc = sym<__half*>(g_sc), *ms = sym<__half*>(g_ms), *m1 = sym<__half*>(g_m1);
    __half *u  = sym<__half*>(g_u);
    float  *scf = sym<float*>(g_scf);
    float  *q2 = sym<float*>(g_q2),  *k2 = sym<float*>(g_k2);
    float  *mm = sym<float*>(g_mm),  *zz = sym<float*>(g_z);
    __half *wqT = sym<__half*>(g_WqT), *wkT = sym<__half*>(g_WkT), *wvT = sym<__half*>(g_WvT);
    __half *wmT = sym<__half*>(g_WmT), *w1T = sym<__half*>(g_W1T), *w2T = sym<__half*>(g_W2T);

    // opt-in to 108KB dynamic smem (idempotent)
    cudaFuncSetAttribute(hgemm_k<0, __half>, cudaFuncAttributeMaxDynamicSharedMemorySize, SMEM_BYTES);
    cudaFuncSetAttribute(hgemm_k<0, float>,  cudaFuncAttributeMaxDynamicSharedMemorySize, SMEM_BYTES);
    cudaFuncSetAttribute(hgemm_k<1, float>,  cudaFuncAttributeMaxDynamicSharedMemorySize, SMEM_BYTES);
    cudaFuncSetAttribute(hgemm_k<2, __half>, cudaFuncAttributeMaxDynamicSharedMemorySize, SMEM_BYTES);

    // 0: fused prep (x/src -> fp16, all weight transposes -> fp16 K-major)
    prep_k<<<XBLK + SBLK + 4*TQ + TW1 + TW2, 256>>>(x, src, xh, sh,
        Wq, Wk, Wv, Wm, W1, W2, wqT, wkT, wvT, wmT, w1T, w2T);

    // 1-2: q/k projections (flattened over batch)
    hgemm_k<0, __half><<<dim3(DM/128, ML/128, 1), 256, SMEM_BYTES>>>(xh, nullptr, wqT, q, DM, DM, DM, DM, 0, 0, 0, nullptr, nullptr, 0, 0);
    hgemm_k<0, __half><<<dim3(DM/128, MS/128, 1), 256, SMEM_BYTES>>>(sh, nullptr, wkT, k, DM, DM, DM, DM, 0, 0, 0, nullptr, nullptr, 0, 0);

    // 3: vT = (src @ Wv)^T computed directly: C[d][s] = sum_k WvT[d][k]*src[s][k]
    hgemm_k<0, __half><<<dim3(SK/128, DM/128, NB), 256, SMEM_BYTES>>>(wvT, nullptr, sh, vT,
        DM, DM, DM, SK, 0, (long)SK*DM, (long)DM*SK, nullptr, nullptr, 0, 0);

    // 4: squared row norms for q and k (one launch)
    rownorm2_k<<<(ML + MS) / 8, 256>>>(q, k, q2, k2);

    // 5: dist = sqrt(max(q2 + k2 - 2 q.k, 0))  (batched NT, fused epilogue, fp32 out)
    hgemm_k<1, float><<<dim3(SK/128, LQ/128, NB), 256, SMEM_BYTES>>>(q, nullptr, k, scf,
        DM, DM, DM, SK, (long)LQ*DM, (long)SK*DM, (long)LQ*SK, q2, k2, LQ, SK);

    // 6: softmax over S (fp32 in, fp16 out)
    softmax_fh<<<ML, 256>>>(scf, sc);

    // 7: message = attn @ v  (A = attn [LQ,SK], B' = vT [DM,SK])
    hgemm_k<0, __half><<<dim3(DM/128, LQ/128, NB), 256, SMEM_BYTES>>>(sc, nullptr, vT, ms,
        SK, SK, SK, DM, (long)LQ*SK, (long)DM*SK, (long)LQ*DM, nullptr, nullptr, 0, 0);

    // 8: mm = message @ Wm  (fp32 out -> layernorm)
    hgemm_k<0, float><<<dim3(DM/128, ML/128, 1), 256, SMEM_BYTES>>>(ms, nullptr, wmT, mm, DM, DM, DM, DM, 0, 0, 0, nullptr, nullptr, 0, 0);

    // 9: layernorm1 -> fp16
    ln_k<__half><<<ML, 256>>>(mm, g1, b1, nullptr, m1);

    // 10: u = relu([x | m1] @ W1)  (fused concat + relu, fp16 out)
    hgemm_k<2, __half><<<dim3(2*DM/128, ML/128, 1), 256, SMEM_BYTES>>>(xh, m1, w1T, u, 2*DM, DM, 2*DM, 2*DM, 0, 0, 0, nullptr, nullptr, 0, 0);

    // 11: z = u @ W2  (fp32 out -> layernorm)
    hgemm_k<0, float><<<dim3(DM/128, ML/128, 1), 256, SMEM_BYTES>>>(u, nullptr, w2T, zz, 2*DM, 2*DM, 2*DM, DM, 0, 0, 0, nullptr, nullptr, 0, 0);

    // 12: out = x + layernorm2(z)
    ln_k<float><<<ML, 256>>>(zz, g2, b2, x, out);
}